// round 8
// baseline (speedup 1.0000x reference)
#include <cuda_runtime.h>
#include <cuda_bf16.h>

#define N_MAX 100000
#define E_MAX 1000000

// ---------------- device scratch ----------------
__device__ float  g_dinv[N_MAX];
__device__ int    g_src[E_MAX];
__device__ int    g_dst[E_MAX];
__device__ int    g_cnt[N_MAX];
__device__ int    g_rowptr[N_MAX + 1];
__device__ int    g_cursor[N_MAX];
__device__ int2   g_csr[E_MAX];                    // {src, weight-as-bits}
__device__ float  g_agg1[(size_t)N_MAX * 64];
__device__ float  g_h1  [(size_t)N_MAX * 128];
__device__ float  g_p2  [(size_t)N_MAX * 64];
__device__ float  g_agg2[(size_t)N_MAX * 64];
__device__ float2 g_pAB [N_MAX];

// ---------------- helpers ----------------
__device__ __forceinline__ unsigned long long fma2(unsigned long long a,
                                                   unsigned long long b,
                                                   unsigned long long c) {
    unsigned long long d;
    asm("fma.rn.f32x2 %0, %1, %2, %3;" : "=l"(d) : "l"(a), "l"(b), "l"(c));
    return d;
}
__device__ __forceinline__ unsigned long long pack2(float x, float y) {
    unsigned long long d;
    asm("mov.b64 %0, {%1, %2};" : "=l"(d) : "f"(x), "f"(y));
    return d;
}
__device__ __forceinline__ void unpack2(unsigned long long v, float& lo, float& hi) {
    asm("mov.b64 {%0, %1}, %2;" : "=f"(lo), "=f"(hi) : "l"(v));
}

// ---------------- kernels ----------------

__global__ void __launch_bounds__(256) k_zero(int N) {
    int i = blockIdx.x * 256 + threadIdx.x;
    if (i < N) g_cnt[i] = 0;
}

// Normalize edge_index (int64 OR int32, runtime-detected) and histogram dst.
__global__ void __launch_bounds__(256) k_convert(const void* __restrict__ ei, int E) {
    long i = (long)blockIdx.x * 256 + threadIdx.x;
    if (i >= E) return;
    const unsigned long long* p64 = (const unsigned long long*)ei;
    bool is64 = true;
#pragma unroll
    for (int j = 0; j < 8; j++) is64 &= (p64[j] < (unsigned long long)N_MAX);
    int s, d;
    if (is64) {
        s = (int)p64[i];
        d = (int)p64[(long)E + i];
    } else {
        const int* p32 = (const int*)ei;
        s = p32[i];
        d = p32[(long)E + i];
    }
    g_src[i] = s;
    g_dst[i] = d;
    atomicAdd(&g_cnt[d], 1);
}

// 1-block exclusive scan over counts -> rowptr/cursor; dinv = rsqrt(deg+1).
__global__ void __launch_bounds__(1024) k_scan(int N, int E) {
    int t = threadIdx.x;
    int C = (N + 1023) >> 10;
    int base = t * C;
    int cnt_sum = 0;
    for (int i = 0; i < C; i++) {
        int idx = base + i;
        if (idx < N) cnt_sum += g_cnt[idx];
    }
    int lane = t & 31, wid = t >> 5;
    int s = cnt_sum;
#pragma unroll
    for (int o = 1; o < 32; o <<= 1) {
        int v = __shfl_up_sync(0xffffffffu, s, o);
        if (lane >= o) s += v;
    }
    __shared__ int wsum[32];
    if (lane == 31) wsum[wid] = s;
    __syncthreads();
    if (wid == 0) {
        int v = wsum[lane];
#pragma unroll
        for (int o = 1; o < 32; o <<= 1) {
            int u = __shfl_up_sync(0xffffffffu, v, o);
            if (lane >= o) v += u;
        }
        wsum[lane] = v;
    }
    __syncthreads();
    int run = s - cnt_sum + (wid > 0 ? wsum[wid - 1] : 0);
    for (int i = 0; i < C; i++) {
        int idx = base + i;
        if (idx < N) {
            int c = g_cnt[idx];
            g_rowptr[idx] = run;
            g_cursor[idx] = run;
            g_dinv[idx] = rsqrtf((float)(c + 1));
            run += c;
        }
    }
    if (t == 0) g_rowptr[N] = E;
}

// Scatter edges into dst-grouped CSR with precomputed norm weight.
__global__ void __launch_bounds__(256) k_scatter(int E) {
    long e = (long)blockIdx.x * 256 + threadIdx.x;
    if (e >= E) return;
    int s = g_src[e], d = g_dst[e];
    int pos = atomicAdd(&g_cursor[d], 1);
    int2 rec;
    rec.x = s;
    rec.y = __float_as_int(g_dinv[s] * g_dinv[d]);
    g_csr[pos] = rec;
}

// CSR aggregation: 16 lanes per node, register accumulation, single write.
// Self-loop folded into the accumulator init: acc = fin[n] * dinv[n]^2.
// which==0: fin = xin (harness pointer), fout = g_agg1
// which==1: fin = g_p2,                  fout = g_agg2
// (globals resolved in DEVICE code — host must never take __device__ addresses)
__global__ void __launch_bounds__(256) k_aggcsr(const float4* __restrict__ xin,
                                                int which, int N) {
    int tid = threadIdx.x;
    int l = tid & 15;
    int n = blockIdx.x * 16 + (tid >> 4);
    if (n >= N) return;
    const float4* fin = which ? (const float4*)g_p2 : xin;
    float4*       fout = which ? (float4*)g_agg2 : (float4*)g_agg1;
    int beg = g_rowptr[n], end = g_rowptr[n + 1];
    float dv = g_dinv[n];
    float w0 = dv * dv;
    float4 acc = __ldg(fin + (size_t)n * 16 + l);
    acc.x *= w0; acc.y *= w0; acc.z *= w0; acc.w *= w0;
    int e = beg;
#pragma unroll 1
    for (; e + 2 <= end; e += 2) {
        int2 a = __ldg(&g_csr[e]);
        int2 b = __ldg(&g_csr[e + 1]);
        float4 v0 = __ldg(fin + (size_t)a.x * 16 + l);
        float4 v1 = __ldg(fin + (size_t)b.x * 16 + l);
        float wa = __int_as_float(a.y);
        float wb = __int_as_float(b.y);
        acc.x += wa * v0.x + wb * v1.x;
        acc.y += wa * v0.y + wb * v1.y;
        acc.z += wa * v0.z + wb * v1.z;
        acc.w += wa * v0.w + wb * v1.w;
    }
    if (e < end) {
        int2 a = __ldg(&g_csr[e]);
        float4 v0 = __ldg(fin + (size_t)a.x * 16 + l);
        float wa = __int_as_float(a.y);
        acc.x += wa * v0.x; acc.y += wa * v0.y;
        acc.z += wa * v0.z; acc.w += wa * v0.w;
    }
    fout[(size_t)n * 16 + l] = acc;
}

// h1 = relu(agg1 @ W1 + b1)   [N,64]x[64,128]
__global__ void __launch_bounds__(256) k_gemm1(const float* __restrict__ W,
                                               const float* __restrict__ b, int N) {
    __shared__ float Ws[64 * 128];
    int tid = threadIdx.x;
    {
        const float4* wv = (const float4*)W;
        float4* sv = (float4*)Ws;
#pragma unroll
        for (int i = 0; i < 8; i++) sv[tid + 256 * i] = wv[tid + 256 * i];
    }
    __syncthreads();
    int tx = tid & 15, ty = tid >> 4;
    int c0 = tx * 8;
    long rowbase = (long)blockIdx.x * 64 + ty * 4;

    long rowc[4];
#pragma unroll
    for (int r = 0; r < 4; r++) {
        long rr = rowbase + r;
        rowc[r] = (rr < N) ? rr : (long)(N - 1);
    }
    unsigned long long acc[4][4];
    {
        float4 b0 = __ldg((const float4*)(b + c0));
        float4 b1 = __ldg((const float4*)(b + c0 + 4));
#pragma unroll
        for (int r = 0; r < 4; r++) {
            acc[r][0] = pack2(b0.x, b0.y);
            acc[r][1] = pack2(b0.z, b0.w);
            acc[r][2] = pack2(b1.x, b1.y);
            acc[r][3] = pack2(b1.z, b1.w);
        }
    }
#pragma unroll 4
    for (int k0 = 0; k0 < 64; k0 += 4) {
        float a_[4][4];
#pragma unroll
        for (int r = 0; r < 4; r++)
            *(float4*)a_[r] = __ldg((const float4*)(g_agg1 + (size_t)rowc[r] * 64 + k0));
#pragma unroll
        for (int kk = 0; kk < 4; kk++) {
            int k = k0 + kk;
            ulonglong2 wa = *(const ulonglong2*)&Ws[k * 128 + c0];
            ulonglong2 wb = *(const ulonglong2*)&Ws[k * 128 + c0 + 4];
#pragma unroll
            for (int r = 0; r < 4; r++) {
                unsigned long long Ar = pack2(a_[r][kk], a_[r][kk]);
                acc[r][0] = fma2(Ar, wa.x, acc[r][0]);
                acc[r][1] = fma2(Ar, wa.y, acc[r][1]);
                acc[r][2] = fma2(Ar, wb.x, acc[r][2]);
                acc[r][3] = fma2(Ar, wb.y, acc[r][3]);
            }
        }
    }
#pragma unroll
    for (int r = 0; r < 4; r++) {
        long row = rowbase + r;
        if (row >= N) break;
        float o[8];
        unpack2(acc[r][0], o[0], o[1]);
        unpack2(acc[r][1], o[2], o[3]);
        unpack2(acc[r][2], o[4], o[5]);
        unpack2(acc[r][3], o[6], o[7]);
#pragma unroll
        for (int j = 0; j < 8; j++) o[j] = fmaxf(o[j], 0.f);
        float* dst = g_h1 + (size_t)row * 128 + c0;
        *(float4*)dst       = make_float4(o[0], o[1], o[2], o[3]);
        *(float4*)(dst + 4) = make_float4(o[4], o[5], o[6], o[7]);
    }
}

// p2 = h1 @ W2 (no bias; layer-2 self-loop handled inside k_aggcsr)
__global__ void __launch_bounds__(256) k_gemm2(const float* __restrict__ W, int N) {
    __shared__ float Ws[128 * 64];
    int tid = threadIdx.x;
    {
        const float4* wv = (const float4*)W;
        float4* sv = (float4*)Ws;
#pragma unroll
        for (int i = 0; i < 8; i++) sv[tid + 256 * i] = wv[tid + 256 * i];
    }
    __syncthreads();
    int tx = tid & 15, ty = tid >> 4;
    int c0 = tx * 4;
    long rowbase = (long)blockIdx.x * 64 + ty * 4;

    long rowc[4];
#pragma unroll
    for (int r = 0; r < 4; r++) {
        long rr = rowbase + r;
        rowc[r] = (rr < N) ? rr : (long)(N - 1);
    }
    unsigned long long acc[4][2];
#pragma unroll
    for (int r = 0; r < 4; r++) { acc[r][0] = 0ull; acc[r][1] = 0ull; }

#pragma unroll 4
    for (int k0 = 0; k0 < 128; k0 += 4) {
        float a_[4][4];
#pragma unroll
        for (int r = 0; r < 4; r++)
            *(float4*)a_[r] = __ldg((const float4*)(g_h1 + (size_t)rowc[r] * 128 + k0));
#pragma unroll
        for (int kk = 0; kk < 4; kk++) {
            int k = k0 + kk;
            ulonglong2 wv = *(const ulonglong2*)&Ws[k * 64 + c0];
#pragma unroll
            for (int r = 0; r < 4; r++) {
                unsigned long long Ar = pack2(a_[r][kk], a_[r][kk]);
                acc[r][0] = fma2(Ar, wv.x, acc[r][0]);
                acc[r][1] = fma2(Ar, wv.y, acc[r][1]);
            }
        }
    }
#pragma unroll
    for (int r = 0; r < 4; r++) {
        long row = rowbase + r;
        if (row >= N) break;
        float o[4];
        unpack2(acc[r][0], o[0], o[1]);
        unpack2(acc[r][1], o[2], o[3]);
        *(float4*)(g_p2 + (size_t)row * 64 + c0) = make_float4(o[0], o[1], o[2], o[3]);
    }
}

// per-node readout: pAB[n] = (dot(relu(agg2+b2), Wc[:64]), dot(relu(agg2+b2), Wc[64:]))
__global__ void __launch_bounds__(256) k_nodescore(const float* __restrict__ Wc,
                                                   const float* __restrict__ b2, int N) {
    int tid = threadIdx.x;
    int l = tid & 15;
    int row = blockIdx.x * 16 + (tid >> 4);
    if (row >= N) return;
    float4 wa = __ldg((const float4*)Wc + l);
    float4 wb = __ldg((const float4*)Wc + 16 + l);
    float4 b4 = __ldg((const float4*)b2 + l);
    float4 v = ((const float4*)g_agg2)[(size_t)row * 16 + l];
    v.x = fmaxf(v.x + b4.x, 0.f); v.y = fmaxf(v.y + b4.y, 0.f);
    v.z = fmaxf(v.z + b4.z, 0.f); v.w = fmaxf(v.w + b4.w, 0.f);
    float pa = v.x * wa.x + v.y * wa.y + v.z * wa.z + v.w * wa.w;
    float pb = v.x * wb.x + v.y * wb.y + v.z * wb.z + v.w * wb.w;
#pragma unroll
    for (int o = 8; o >= 1; o >>= 1) {
        pa += __shfl_down_sync(0xffffffffu, pa, o, 16);
        pb += __shfl_down_sync(0xffffffffu, pb, o, 16);
    }
    if (l == 0) g_pAB[row] = make_float2(pa, pb);
}

__global__ void __launch_bounds__(256) k_edge(const float* __restrict__ bcp,
                                              float* __restrict__ out, int E) {
    long e = (long)blockIdx.x * 256 + threadIdx.x;
    if (e >= E) return;
    int s = g_src[e], d = g_dst[e];
    float2 ps = __ldg(&g_pAB[s]);
    float2 pd = __ldg(&g_pAB[d]);
    float z = ps.x + pd.y + __ldg(bcp);
    out[e] = 1.0f / (1.0f + __expf(-z));
}

// ---------------- launcher ----------------
extern "C" void kernel_launch(void* const* d_in, const int* in_sizes, int n_in,
                              void* d_out, int out_size) {
    const float* x  = (const float*)d_in[0];
    const void*  ei = d_in[1];
    const float* W1 = (const float*)d_in[2];
    const float* b1 = (const float*)d_in[3];
    const float* W2 = (const float*)d_in[4];
    const float* b2 = (const float*)d_in[5];
    const float* Wc = (const float*)d_in[6];
    const float* bc = (const float*)d_in[7];
    float* out = (float*)d_out;

    int N = in_sizes[0] / 64;
    int E = in_sizes[1] / 2;
    if (N > N_MAX) N = N_MAX;
    if (E > E_MAX) E = E_MAX;

    int nb16 = (N + 15) / 16;
    int gb   = (N + 63) / 64;
    int ebs  = (E + 255) / 256;

    k_zero     <<<(N + 255) / 256, 256>>>(N);
    k_convert  <<<ebs, 256>>>(ei, E);
    k_scan     <<<1, 1024>>>(N, E);
    k_scatter  <<<ebs, 256>>>(E);
    k_aggcsr   <<<nb16, 256>>>((const float4*)x, 0, N);
    k_gemm1    <<<gb, 256>>>(W1, b1, N);
    k_gemm2    <<<gb, 256>>>(W2, N);
    k_aggcsr   <<<nb16, 256>>>((const float4*)x, 1, N);
    k_nodescore<<<nb16, 256>>>(Wc, b2, N);
    k_edge     <<<ebs, 256>>>(bc, out, E);
}

// round 9
// speedup vs baseline: 1.1796x; 1.1796x over previous
#include <cuda_runtime.h>
#include <cuda_bf16.h>

#define N_MAX 100000
#define E_MAX 1000000

// ---------------- device scratch ----------------
__device__ float  g_dinv[N_MAX];
__device__ int    g_src[E_MAX];
__device__ int    g_dst[E_MAX];
__device__ int    g_cnt[N_MAX];
__device__ int    g_rowptr[N_MAX + 1];
__device__ int    g_cursor[N_MAX];
__device__ int2   g_csr[E_MAX];                    // {src, weight-as-bits}
__device__ float  g_agg1[(size_t)N_MAX * 64];
__device__ float  g_h1  [(size_t)N_MAX * 128];
__device__ float  g_p2  [(size_t)N_MAX * 64];
__device__ float2 g_pAB [N_MAX];

// ---------------- helpers ----------------
__device__ __forceinline__ unsigned long long fma2(unsigned long long a,
                                                   unsigned long long b,
                                                   unsigned long long c) {
    unsigned long long d;
    asm("fma.rn.f32x2 %0, %1, %2, %3;" : "=l"(d) : "l"(a), "l"(b), "l"(c));
    return d;
}
__device__ __forceinline__ unsigned long long pack2(float x, float y) {
    unsigned long long d;
    asm("mov.b64 %0, {%1, %2};" : "=l"(d) : "f"(x), "f"(y));
    return d;
}
__device__ __forceinline__ void unpack2(unsigned long long v, float& lo, float& hi) {
    asm("mov.b64 {%0, %1}, %2;" : "=f"(lo), "=f"(hi) : "l"(v));
}

// ---------------- kernels ----------------

__global__ void __launch_bounds__(256) k_zero(int N) {
    int i = blockIdx.x * 256 + threadIdx.x;
    if (i < N) g_cnt[i] = 0;
}

// Normalize edge_index (int64 OR int32, runtime-detected) and histogram dst.
__global__ void __launch_bounds__(256) k_convert(const void* __restrict__ ei, int E) {
    long i = (long)blockIdx.x * 256 + threadIdx.x;
    if (i >= E) return;
    const unsigned long long* p64 = (const unsigned long long*)ei;
    bool is64 = true;
#pragma unroll
    for (int j = 0; j < 8; j++) is64 &= (p64[j] < (unsigned long long)N_MAX);
    int s, d;
    if (is64) {
        s = (int)p64[i];
        d = (int)p64[(long)E + i];
    } else {
        const int* p32 = (const int*)ei;
        s = p32[i];
        d = p32[(long)E + i];
    }
    g_src[i] = s;
    g_dst[i] = d;
    atomicAdd(&g_cnt[d], 1);
}

// 1-block exclusive scan (INT ONLY — no MUFU work here).
__global__ void __launch_bounds__(1024) k_scan(int N, int E) {
    int t = threadIdx.x;
    int C = (N + 1023) >> 10;
    int base = t * C;
    int cnt_sum = 0;
    for (int i = 0; i < C; i++) {
        int idx = base + i;
        if (idx < N) cnt_sum += g_cnt[idx];
    }
    int lane = t & 31, wid = t >> 5;
    int s = cnt_sum;
#pragma unroll
    for (int o = 1; o < 32; o <<= 1) {
        int v = __shfl_up_sync(0xffffffffu, s, o);
        if (lane >= o) s += v;
    }
    __shared__ int wsum[32];
    if (lane == 31) wsum[wid] = s;
    __syncthreads();
    if (wid == 0) {
        int v = wsum[lane];
#pragma unroll
        for (int o = 1; o < 32; o <<= 1) {
            int u = __shfl_up_sync(0xffffffffu, v, o);
            if (lane >= o) v += u;
        }
        wsum[lane] = v;
    }
    __syncthreads();
    int run = s - cnt_sum + (wid > 0 ? wsum[wid - 1] : 0);
    for (int i = 0; i < C; i++) {
        int idx = base + i;
        if (idx < N) {
            int c = g_cnt[idx];
            g_rowptr[idx] = run;
            g_cursor[idx] = run;
            run += c;
        }
    }
    if (t == 0) g_rowptr[N] = E;
}

// Parallel dinv = rsqrt(deg+1) — full-chip MUFU, not single-block.
__global__ void __launch_bounds__(256) k_dinv(int N) {
    int i = blockIdx.x * 256 + threadIdx.x;
    if (i < N) g_dinv[i] = rsqrtf((float)(g_cnt[i] + 1));
}

// Scatter edges into dst-grouped CSR with precomputed norm weight.
__global__ void __launch_bounds__(256) k_scatter(int E) {
    long e = (long)blockIdx.x * 256 + threadIdx.x;
    if (e >= E) return;
    int s = g_src[e], d = g_dst[e];
    int pos = atomicAdd(&g_cursor[d], 1);
    int2 rec;
    rec.x = s;
    rec.y = __float_as_int(g_dinv[s] * g_dinv[d]);
    g_csr[pos] = rec;
}

// CSR aggregation: 16 lanes per node, register accumulation, MLP-4 pipeline.
// Self-loop folded into accumulator init: acc = fin[n] * dinv[n]^2.
// which==0: fin = xin,  out = g_agg1 (single float4 store)
// which==1: fin = g_p2, out = fused node readout -> g_pAB (agg2 never hits memory)
__global__ void __launch_bounds__(256) k_aggcsr(const float4* __restrict__ xin,
                                                int which, int N,
                                                const float* __restrict__ Wc,
                                                const float* __restrict__ b2) {
    int tid = threadIdx.x;
    int l = tid & 15;
    int n = blockIdx.x * 16 + (tid >> 4);
    if (n >= N) return;
    const float4* fin = which ? (const float4*)g_p2 : xin;
    int beg = g_rowptr[n], end = g_rowptr[n + 1];
    float dv = g_dinv[n];
    float w0 = dv * dv;
    float4 acc = __ldg(fin + (size_t)n * 16 + l);
    acc.x *= w0; acc.y *= w0; acc.z *= w0; acc.w *= w0;
    int e = beg;
#pragma unroll 1
    for (; e + 4 <= end; e += 4) {
        int2 a0 = __ldg(&g_csr[e]);
        int2 a1 = __ldg(&g_csr[e + 1]);
        int2 a2 = __ldg(&g_csr[e + 2]);
        int2 a3 = __ldg(&g_csr[e + 3]);
        float4 v0 = __ldg(fin + (size_t)a0.x * 16 + l);
        float4 v1 = __ldg(fin + (size_t)a1.x * 16 + l);
        float4 v2 = __ldg(fin + (size_t)a2.x * 16 + l);
        float4 v3 = __ldg(fin + (size_t)a3.x * 16 + l);
        float w0_ = __int_as_float(a0.y), w1_ = __int_as_float(a1.y);
        float w2_ = __int_as_float(a2.y), w3_ = __int_as_float(a3.y);
        acc.x += w0_ * v0.x + w1_ * v1.x + w2_ * v2.x + w3_ * v3.x;
        acc.y += w0_ * v0.y + w1_ * v1.y + w2_ * v2.y + w3_ * v3.y;
        acc.z += w0_ * v0.z + w1_ * v1.z + w2_ * v2.z + w3_ * v3.z;
        acc.w += w0_ * v0.w + w1_ * v1.w + w2_ * v2.w + w3_ * v3.w;
    }
#pragma unroll 1
    for (; e < end; e++) {
        int2 a = __ldg(&g_csr[e]);
        float4 v0 = __ldg(fin + (size_t)a.x * 16 + l);
        float wa = __int_as_float(a.y);
        acc.x += wa * v0.x; acc.y += wa * v0.y;
        acc.z += wa * v0.z; acc.w += wa * v0.w;
    }
    if (which == 0) {
        ((float4*)g_agg1)[(size_t)n * 16 + l] = acc;
    } else {
        // fused node readout: pAB[n] = (relu(acc+b2).Wc[:64], relu(acc+b2).Wc[64:])
        float4 wa = __ldg((const float4*)Wc + l);
        float4 wb = __ldg((const float4*)Wc + 16 + l);
        float4 b4 = __ldg((const float4*)b2 + l);
        acc.x = fmaxf(acc.x + b4.x, 0.f); acc.y = fmaxf(acc.y + b4.y, 0.f);
        acc.z = fmaxf(acc.z + b4.z, 0.f); acc.w = fmaxf(acc.w + b4.w, 0.f);
        float pa = acc.x * wa.x + acc.y * wa.y + acc.z * wa.z + acc.w * wa.w;
        float pb = acc.x * wb.x + acc.y * wb.y + acc.z * wb.z + acc.w * wb.w;
#pragma unroll
        for (int o = 8; o >= 1; o >>= 1) {
            pa += __shfl_down_sync(0xffffffffu, pa, o, 16);
            pb += __shfl_down_sync(0xffffffffu, pb, o, 16);
        }
        if (l == 0) g_pAB[n] = make_float2(pa, pb);
    }
}

// h1 = relu(agg1 @ W1 + b1)   [N,64]x[64,128]
__global__ void __launch_bounds__(256) k_gemm1(const float* __restrict__ W,
                                               const float* __restrict__ b, int N) {
    __shared__ float Ws[64 * 128];
    int tid = threadIdx.x;
    {
        const float4* wv = (const float4*)W;
        float4* sv = (float4*)Ws;
#pragma unroll
        for (int i = 0; i < 8; i++) sv[tid + 256 * i] = wv[tid + 256 * i];
    }
    __syncthreads();
    int tx = tid & 15, ty = tid >> 4;
    int c0 = tx * 8;
    long rowbase = (long)blockIdx.x * 64 + ty * 4;

    long rowc[4];
#pragma unroll
    for (int r = 0; r < 4; r++) {
        long rr = rowbase + r;
        rowc[r] = (rr < N) ? rr : (long)(N - 1);
    }
    unsigned long long acc[4][4];
    {
        float4 b0 = __ldg((const float4*)(b + c0));
        float4 b1 = __ldg((const float4*)(b + c0 + 4));
#pragma unroll
        for (int r = 0; r < 4; r++) {
            acc[r][0] = pack2(b0.x, b0.y);
            acc[r][1] = pack2(b0.z, b0.w);
            acc[r][2] = pack2(b1.x, b1.y);
            acc[r][3] = pack2(b1.z, b1.w);
        }
    }
#pragma unroll 4
    for (int k0 = 0; k0 < 64; k0 += 4) {
        float a_[4][4];
#pragma unroll
        for (int r = 0; r < 4; r++)
            *(float4*)a_[r] = __ldg((const float4*)(g_agg1 + (size_t)rowc[r] * 64 + k0));
#pragma unroll
        for (int kk = 0; kk < 4; kk++) {
            int k = k0 + kk;
            ulonglong2 wa = *(const ulonglong2*)&Ws[k * 128 + c0];
            ulonglong2 wb = *(const ulonglong2*)&Ws[k * 128 + c0 + 4];
#pragma unroll
            for (int r = 0; r < 4; r++) {
                unsigned long long Ar = pack2(a_[r][kk], a_[r][kk]);
                acc[r][0] = fma2(Ar, wa.x, acc[r][0]);
                acc[r][1] = fma2(Ar, wa.y, acc[r][1]);
                acc[r][2] = fma2(Ar, wb.x, acc[r][2]);
                acc[r][3] = fma2(Ar, wb.y, acc[r][3]);
            }
        }
    }
#pragma unroll
    for (int r = 0; r < 4; r++) {
        long row = rowbase + r;
        if (row >= N) break;
        float o[8];
        unpack2(acc[r][0], o[0], o[1]);
        unpack2(acc[r][1], o[2], o[3]);
        unpack2(acc[r][2], o[4], o[5]);
        unpack2(acc[r][3], o[6], o[7]);
#pragma unroll
        for (int j = 0; j < 8; j++) o[j] = fmaxf(o[j], 0.f);
        float* dst = g_h1 + (size_t)row * 128 + c0;
        *(float4*)dst       = make_float4(o[0], o[1], o[2], o[3]);
        *(float4*)(dst + 4) = make_float4(o[4], o[5], o[6], o[7]);
    }
}

// p2 = h1 @ W2 (no bias; layer-2 self-loop handled inside k_aggcsr)
__global__ void __launch_bounds__(256) k_gemm2(const float* __restrict__ W, int N) {
    __shared__ float Ws[128 * 64];
    int tid = threadIdx.x;
    {
        const float4* wv = (const float4*)W;
        float4* sv = (float4*)Ws;
#pragma unroll
        for (int i = 0; i < 8; i++) sv[tid + 256 * i] = wv[tid + 256 * i];
    }
    __syncthreads();
    int tx = tid & 15, ty = tid >> 4;
    int c0 = tx * 4;
    long rowbase = (long)blockIdx.x * 64 + ty * 4;

    long rowc[4];
#pragma unroll
    for (int r = 0; r < 4; r++) {
        long rr = rowbase + r;
        rowc[r] = (rr < N) ? rr : (long)(N - 1);
    }
    unsigned long long acc[4][2];
#pragma unroll
    for (int r = 0; r < 4; r++) { acc[r][0] = 0ull; acc[r][1] = 0ull; }

#pragma unroll 4
    for (int k0 = 0; k0 < 128; k0 += 4) {
        float a_[4][4];
#pragma unroll
        for (int r = 0; r < 4; r++)
            *(float4*)a_[r] = __ldg((const float4*)(g_h1 + (size_t)rowc[r] * 128 + k0));
#pragma unroll
        for (int kk = 0; kk < 4; kk++) {
            int k = k0 + kk;
            ulonglong2 wv = *(const ulonglong2*)&Ws[k * 64 + c0];
#pragma unroll
            for (int r = 0; r < 4; r++) {
                unsigned long long Ar = pack2(a_[r][kk], a_[r][kk]);
                acc[r][0] = fma2(Ar, wv.x, acc[r][0]);
                acc[r][1] = fma2(Ar, wv.y, acc[r][1]);
            }
        }
    }
#pragma unroll
    for (int r = 0; r < 4; r++) {
        long row = rowbase + r;
        if (row >= N) break;
        float o[4];
        unpack2(acc[r][0], o[0], o[1]);
        unpack2(acc[r][1], o[2], o[3]);
        *(float4*)(g_p2 + (size_t)row * 64 + c0) = make_float4(o[0], o[1], o[2], o[3]);
    }
}

__global__ void __launch_bounds__(256) k_edge(const float* __restrict__ bcp,
                                              float* __restrict__ out, int E) {
    long e = (long)blockIdx.x * 256 + threadIdx.x;
    if (e >= E) return;
    int s = g_src[e], d = g_dst[e];
    float2 ps = __ldg(&g_pAB[s]);
    float2 pd = __ldg(&g_pAB[d]);
    float z = ps.x + pd.y + __ldg(bcp);
    out[e] = 1.0f / (1.0f + __expf(-z));
}

// ---------------- launcher ----------------
extern "C" void kernel_launch(void* const* d_in, const int* in_sizes, int n_in,
                              void* d_out, int out_size) {
    const float* x  = (const float*)d_in[0];
    const void*  ei = d_in[1];
    const float* W1 = (const float*)d_in[2];
    const float* b1 = (const float*)d_in[3];
    const float* W2 = (const float*)d_in[4];
    const float* b2 = (const float*)d_in[5];
    const float* Wc = (const float*)d_in[6];
    const float* bc = (const float*)d_in[7];
    float* out = (float*)d_out;

    int N = in_sizes[0] / 64;
    int E = in_sizes[1] / 2;
    if (N > N_MAX) N = N_MAX;
    if (E > E_MAX) E = E_MAX;

    int nb16 = (N + 15) / 16;
    int gb   = (N + 63) / 64;
    int ebs  = (E + 255) / 256;
    int nbs  = (N + 255) / 256;

    k_zero   <<<nbs, 256>>>(N);
    k_convert<<<ebs, 256>>>(ei, E);
    k_scan   <<<1, 1024>>>(N, E);
    k_dinv   <<<nbs, 256>>>(N);
    k_scatter<<<ebs, 256>>>(E);
    k_aggcsr <<<nb16, 256>>>((const float4*)x, 0, N, Wc, b2);
    k_gemm1  <<<gb, 256>>>(W1, b1, N);
    k_gemm2  <<<gb, 256>>>(W2, N);
    k_aggcsr <<<nb16, 256>>>((const float4*)x, 1, N, Wc, b2);
    k_edge   <<<ebs, 256>>>(bc, out, E);
}

// round 10
// speedup vs baseline: 1.6409x; 1.3910x over previous
#include <cuda_runtime.h>
#include <cuda_bf16.h>

#define N_MAX 100000
#define E_MAX 1000000

// ---------------- device scratch ----------------
__device__ float  g_dinv[N_MAX];
__device__ int    g_src[E_MAX + 4];   // +4 pad: int4 index loads at the tail
__device__ int    g_dst[E_MAX + 4];
__device__ float  g_agg1[(size_t)N_MAX * 64];
__device__ float  g_h1  [(size_t)N_MAX * 128];
__device__ float  g_p2  [(size_t)N_MAX * 64];
__device__ float  g_agg2[(size_t)N_MAX * 64];
__device__ float2 g_pAB [N_MAX];

// ---------------- helpers ----------------
__device__ __forceinline__ void red_add_v4(float* p, float4 v) {
    asm volatile("red.global.add.v4.f32 [%0], {%1, %2, %3, %4};"
                 :: "l"(p), "f"(v.x), "f"(v.y), "f"(v.z), "f"(v.w)
                 : "memory");
}
__device__ __forceinline__ unsigned long long fma2(unsigned long long a,
                                                   unsigned long long b,
                                                   unsigned long long c) {
    unsigned long long d;
    asm("fma.rn.f32x2 %0, %1, %2, %3;" : "=l"(d) : "l"(a), "l"(b), "l"(c));
    return d;
}
__device__ __forceinline__ unsigned long long pack2(float x, float y) {
    unsigned long long d;
    asm("mov.b64 %0, {%1, %2};" : "=l"(d) : "f"(x), "f"(y));
    return d;
}
__device__ __forceinline__ void unpack2(unsigned long long v, float& lo, float& hi) {
    asm("mov.b64 {%0, %1}, %2;" : "=f"(lo), "=f"(hi) : "l"(v));
}

// ---------------- kernels ----------------

__global__ void __launch_bounds__(256) k_deg_init(int N) {
    int i = blockIdx.x * 256 + threadIdx.x;
    if (i < N) g_dinv[i] = 1.0f;                  // self-loop
}

// Normalize edge_index (int64 OR int32, runtime-detected) + degree count at dst.
__global__ void __launch_bounds__(256) k_convert(const void* __restrict__ ei, int E) {
    long i = (long)blockIdx.x * 256 + threadIdx.x;
    if (i >= E) return;
    const unsigned long long* p64 = (const unsigned long long*)ei;
    bool is64 = true;
#pragma unroll
    for (int j = 0; j < 8; j++) is64 &= (p64[j] < (unsigned long long)N_MAX);
    int s, d;
    if (is64) {
        s = (int)p64[i];
        d = (int)p64[(long)E + i];
    } else {
        const int* p32 = (const int*)ei;
        s = p32[i];
        d = p32[(long)E + i];
    }
    g_src[i] = s;
    g_dst[i] = d;
    atomicAdd(&g_dinv[d], 1.0f);
}

// dinv = rsqrt(deg); agg1[i] = x[i]/deg[i]  (self-loop term)
__global__ void __launch_bounds__(256) k_selfinit(const float* __restrict__ x, int N) {
    int tid = threadIdx.x;
    int l = tid & 15;
    int row = blockIdx.x * 16 + (tid >> 4);
    if (row >= N) return;
    float dv = rsqrtf(g_dinv[row]);
    if (l == 0) g_dinv[row] = dv;
    float w = dv * dv;
    float4 v = __ldg((const float4*)x + (size_t)row * 16 + l);
    v.x *= w; v.y *= w; v.z *= w; v.w *= w;
    ((float4*)g_agg1)[(size_t)row * 16 + l] = v;
}

// Edge aggregation: 4 consecutive edges per 16-lane group.
// Index loads become two broadcast LDG.128; 4 gathers + 4 red.v4 issue with MLP=4.
__global__ void __launch_bounds__(256) k_agg(const float* __restrict__ xin, int E, int which) {
    int tid = threadIdx.x;
    int l = tid & 15;
    long g = (long)blockIdx.x * 16 + (tid >> 4);
    long e0 = g * 4;
    if (e0 >= E) return;
    const float4* f4 = which ? (const float4*)g_p2 : (const float4*)xin;
    float*        ob = which ? g_agg2 : g_agg1;
    int4 ss = *(const int4*)(g_src + e0);   // padded arrays: safe at tail
    int4 dd = *(const int4*)(g_dst + e0);
    if (e0 + 4 <= E) {
        // fast path: full group of 4 edges
        float ws0 = g_dinv[ss.x], ws1 = g_dinv[ss.y];
        float ws2 = g_dinv[ss.z], ws3 = g_dinv[ss.w];
        float wd0 = g_dinv[dd.x], wd1 = g_dinv[dd.y];
        float wd2 = g_dinv[dd.z], wd3 = g_dinv[dd.w];
        float4 v0 = __ldg(f4 + (size_t)ss.x * 16 + l);
        float4 v1 = __ldg(f4 + (size_t)ss.y * 16 + l);
        float4 v2 = __ldg(f4 + (size_t)ss.z * 16 + l);
        float4 v3 = __ldg(f4 + (size_t)ss.w * 16 + l);
        float w0 = ws0 * wd0, w1 = ws1 * wd1, w2 = ws2 * wd2, w3 = ws3 * wd3;
        v0.x *= w0; v0.y *= w0; v0.z *= w0; v0.w *= w0;
        v1.x *= w1; v1.y *= w1; v1.z *= w1; v1.w *= w1;
        v2.x *= w2; v2.y *= w2; v2.z *= w2; v2.w *= w2;
        v3.x *= w3; v3.y *= w3; v3.z *= w3; v3.w *= w3;
        red_add_v4(ob + (size_t)dd.x * 64 + l * 4, v0);
        red_add_v4(ob + (size_t)dd.y * 64 + l * 4, v1);
        red_add_v4(ob + (size_t)dd.z * 64 + l * 4, v2);
        red_add_v4(ob + (size_t)dd.w * 64 + l * 4, v3);
    } else {
        int rem = (int)(E - e0);
        int sa[4] = {ss.x, ss.y, ss.z, ss.w};
        int da[4] = {dd.x, dd.y, dd.z, dd.w};
#pragma unroll 1
        for (int k = 0; k < rem; k++) {
            int s = sa[k], d = da[k];
            float w = g_dinv[s] * g_dinv[d];
            float4 v = __ldg(f4 + (size_t)s * 16 + l);
            v.x *= w; v.y *= w; v.z *= w; v.w *= w;
            red_add_v4(ob + (size_t)d * 64 + l * 4, v);
        }
    }
}

// h1 = relu(agg1 @ W1 + b1)   [N,64]x[64,128]
__global__ void __launch_bounds__(256) k_gemm1(const float* __restrict__ W,
                                               const float* __restrict__ b, int N) {
    __shared__ float Ws[64 * 128];
    int tid = threadIdx.x;
    {
        const float4* wv = (const float4*)W;
        float4* sv = (float4*)Ws;
#pragma unroll
        for (int i = 0; i < 8; i++) sv[tid + 256 * i] = wv[tid + 256 * i];
    }
    __syncthreads();
    int tx = tid & 15, ty = tid >> 4;
    int c0 = tx * 8;
    long rowbase = (long)blockIdx.x * 64 + ty * 4;

    long rowc[4];
#pragma unroll
    for (int r = 0; r < 4; r++) {
        long rr = rowbase + r;
        rowc[r] = (rr < N) ? rr : (long)(N - 1);
    }
    unsigned long long acc[4][4];
    {
        float4 b0 = __ldg((const float4*)(b + c0));
        float4 b1 = __ldg((const float4*)(b + c0 + 4));
#pragma unroll
        for (int r = 0; r < 4; r++) {
            acc[r][0] = pack2(b0.x, b0.y);
            acc[r][1] = pack2(b0.z, b0.w);
            acc[r][2] = pack2(b1.x, b1.y);
            acc[r][3] = pack2(b1.z, b1.w);
        }
    }
#pragma unroll 4
    for (int k0 = 0; k0 < 64; k0 += 4) {
        float a_[4][4];
#pragma unroll
        for (int r = 0; r < 4; r++)
            *(float4*)a_[r] = __ldg((const float4*)(g_agg1 + (size_t)rowc[r] * 64 + k0));
#pragma unroll
        for (int kk = 0; kk < 4; kk++) {
            int k = k0 + kk;
            ulonglong2 wa = *(const ulonglong2*)&Ws[k * 128 + c0];
            ulonglong2 wb = *(const ulonglong2*)&Ws[k * 128 + c0 + 4];
#pragma unroll
            for (int r = 0; r < 4; r++) {
                unsigned long long Ar = pack2(a_[r][kk], a_[r][kk]);
                acc[r][0] = fma2(Ar, wa.x, acc[r][0]);
                acc[r][1] = fma2(Ar, wa.y, acc[r][1]);
                acc[r][2] = fma2(Ar, wb.x, acc[r][2]);
                acc[r][3] = fma2(Ar, wb.y, acc[r][3]);
            }
        }
    }
#pragma unroll
    for (int r = 0; r < 4; r++) {
        long row = rowbase + r;
        if (row >= N) break;
        float o[8];
        unpack2(acc[r][0], o[0], o[1]);
        unpack2(acc[r][1], o[2], o[3]);
        unpack2(acc[r][2], o[4], o[5]);
        unpack2(acc[r][3], o[6], o[7]);
#pragma unroll
        for (int j = 0; j < 8; j++) o[j] = fmaxf(o[j], 0.f);
        float* dst = g_h1 + (size_t)row * 128 + c0;
        *(float4*)dst       = make_float4(o[0], o[1], o[2], o[3]);
        *(float4*)(dst + 4) = make_float4(o[4], o[5], o[6], o[7]);
    }
}

// p2 = h1 @ W2 (no bias); agg2 = p2 * dinv^2 (fused self-loop init)
__global__ void __launch_bounds__(256) k_gemm2(const float* __restrict__ W, int N) {
    __shared__ float Ws[128 * 64];
    int tid = threadIdx.x;
    {
        const float4* wv = (const float4*)W;
        float4* sv = (float4*)Ws;
#pragma unroll
        for (int i = 0; i < 8; i++) sv[tid + 256 * i] = wv[tid + 256 * i];
    }
    __syncthreads();
    int tx = tid & 15, ty = tid >> 4;
    int c0 = tx * 4;
    long rowbase = (long)blockIdx.x * 64 + ty * 4;

    long rowc[4];
#pragma unroll
    for (int r = 0; r < 4; r++) {
        long rr = rowbase + r;
        rowc[r] = (rr < N) ? rr : (long)(N - 1);
    }
    unsigned long long acc[4][2];
#pragma unroll
    for (int r = 0; r < 4; r++) { acc[r][0] = 0ull; acc[r][1] = 0ull; }

#pragma unroll 4
    for (int k0 = 0; k0 < 128; k0 += 4) {
        float a_[4][4];
#pragma unroll
        for (int r = 0; r < 4; r++)
            *(float4*)a_[r] = __ldg((const float4*)(g_h1 + (size_t)rowc[r] * 128 + k0));
#pragma unroll
        for (int kk = 0; kk < 4; kk++) {
            int k = k0 + kk;
            ulonglong2 wv = *(const ulonglong2*)&Ws[k * 64 + c0];
#pragma unroll
            for (int r = 0; r < 4; r++) {
                unsigned long long Ar = pack2(a_[r][kk], a_[r][kk]);
                acc[r][0] = fma2(Ar, wv.x, acc[r][0]);
                acc[r][1] = fma2(Ar, wv.y, acc[r][1]);
            }
        }
    }
#pragma unroll
    for (int r = 0; r < 4; r++) {
        long row = rowbase + r;
        if (row >= N) break;
        float o[4];
        unpack2(acc[r][0], o[0], o[1]);
        unpack2(acc[r][1], o[2], o[3]);
        float4 po = make_float4(o[0], o[1], o[2], o[3]);
        *(float4*)(g_p2 + (size_t)row * 64 + c0) = po;
        float dv = g_dinv[row];
        float w = dv * dv;
        po.x *= w; po.y *= w; po.z *= w; po.w *= w;
        *(float4*)(g_agg2 + (size_t)row * 64 + c0) = po;
    }
}

// per-node readout: pAB[n] = (dot(relu(agg2+b2), Wc[:64]), dot(relu(agg2+b2), Wc[64:]))
__global__ void __launch_bounds__(256) k_nodescore(const float* __restrict__ Wc,
                                                   const float* __restrict__ b2, int N) {
    int tid = threadIdx.x;
    int l = tid & 15;
    int row = blockIdx.x * 16 + (tid >> 4);
    if (row >= N) return;
    float4 wa = __ldg((const float4*)Wc + l);
    float4 wb = __ldg((const float4*)Wc + 16 + l);
    float4 b4 = __ldg((const float4*)b2 + l);
    float4 v = ((const float4*)g_agg2)[(size_t)row * 16 + l];
    v.x = fmaxf(v.x + b4.x, 0.f); v.y = fmaxf(v.y + b4.y, 0.f);
    v.z = fmaxf(v.z + b4.z, 0.f); v.w = fmaxf(v.w + b4.w, 0.f);
    float pa = v.x * wa.x + v.y * wa.y + v.z * wa.z + v.w * wa.w;
    float pb = v.x * wb.x + v.y * wb.y + v.z * wb.z + v.w * wb.w;
#pragma unroll
    for (int o = 8; o >= 1; o >>= 1) {
        pa += __shfl_down_sync(0xffffffffu, pa, o, 16);
        pb += __shfl_down_sync(0xffffffffu, pb, o, 16);
    }
    if (l == 0) g_pAB[row] = make_float2(pa, pb);
}

__global__ void __launch_bounds__(256) k_edge(const float* __restrict__ bcp,
                                              float* __restrict__ out, int E) {
    long e = (long)blockIdx.x * 256 + threadIdx.x;
    if (e >= E) return;
    int s = g_src[e], d = g_dst[e];
    float2 ps = __ldg(&g_pAB[s]);
    float2 pd = __ldg(&g_pAB[d]);
    float z = ps.x + pd.y + __ldg(bcp);
    out[e] = 1.0f / (1.0f + __expf(-z));
}

// ---------------- launcher ----------------
extern "C" void kernel_launch(void* const* d_in, const int* in_sizes, int n_in,
                              void* d_out, int out_size) {
    const float* x  = (const float*)d_in[0];
    const void*  ei = d_in[1];
    const float* W1 = (const float*)d_in[2];
    const float* b1 = (const float*)d_in[3];
    const float* W2 = (const float*)d_in[4];
    const float* b2 = (const float*)d_in[5];
    const float* Wc = (const float*)d_in[6];
    const float* bc = (const float*)d_in[7];
    float* out = (float*)d_out;

    int N = in_sizes[0] / 64;
    int E = in_sizes[1] / 2;
    if (N > N_MAX) N = N_MAX;
    if (E > E_MAX) E = E_MAX;

    long groups = ((long)E + 3) / 4;
    int  eb4  = (int)((groups + 15) / 16);   // 16 groups (64 edges) per block
    int  nb16 = (N + 15) / 16;
    int  gb   = (N + 63) / 64;
    int  ebs  = (E + 255) / 256;

    k_deg_init <<<(N + 255) / 256, 256>>>(N);
    k_convert  <<<ebs, 256>>>(ei, E);
    k_selfinit <<<nb16, 256>>>(x, N);
    k_agg      <<<eb4, 256>>>(x, E, 0);
    k_gemm1    <<<gb, 256>>>(W1, b1, N);
    k_gemm2    <<<gb, 256>>>(W2, N);
    k_agg      <<<eb4, 256>>>(x, E, 1);
    k_nodescore<<<nb16, 256>>>(Wc, b2, N);
    k_edge     <<<ebs, 256>>>(bc, out, E);
}

// round 11
// speedup vs baseline: 1.6893x; 1.0295x over previous
#include <cuda_runtime.h>
#include <cuda_fp16.h>
#include <cuda_bf16.h>

#define N_MAX 100000
#define E_MAX 1000000

// ---------------- device scratch ----------------
__device__ float  g_dinv[N_MAX];
__device__ int    g_src[E_MAX + 4];   // +4 pad: int4 index loads at the tail
__device__ int    g_dst[E_MAX + 4];
__device__ float  g_agg1[(size_t)N_MAX * 64];
__device__ float  g_h1  [(size_t)N_MAX * 128];
__device__ float  g_agg2[(size_t)N_MAX * 64];
__device__ uint2  g_xh  [(size_t)N_MAX * 16];   // x  as fp16 (64 feats = 16 uint2)
__device__ uint2  g_p2h [(size_t)N_MAX * 16];   // p2 as fp16
__device__ float2 g_pAB [N_MAX];

// ---------------- helpers ----------------
__device__ __forceinline__ void red_add_v4(float* p, float4 v) {
    asm volatile("red.global.add.v4.f32 [%0], {%1, %2, %3, %4};"
                 :: "l"(p), "f"(v.x), "f"(v.y), "f"(v.z), "f"(v.w)
                 : "memory");
}
__device__ __forceinline__ unsigned long long fma2(unsigned long long a,
                                                   unsigned long long b,
                                                   unsigned long long c) {
    unsigned long long d;
    asm("fma.rn.f32x2 %0, %1, %2, %3;" : "=l"(d) : "l"(a), "l"(b), "l"(c));
    return d;
}
__device__ __forceinline__ unsigned long long pack2(float x, float y) {
    unsigned long long d;
    asm("mov.b64 %0, {%1, %2};" : "=l"(d) : "f"(x), "f"(y));
    return d;
}
__device__ __forceinline__ void unpack2(unsigned long long v, float& lo, float& hi) {
    asm("mov.b64 {%0, %1}, %2;" : "=f"(lo), "=f"(hi) : "l"(v));
}
__device__ __forceinline__ uint2 to_h4(float4 v) {
    __half2 a = __floats2half2_rn(v.x, v.y);
    __half2 b = __floats2half2_rn(v.z, v.w);
    uint2 u;
    u.x = *reinterpret_cast<unsigned int*>(&a);
    u.y = *reinterpret_cast<unsigned int*>(&b);
    return u;
}
__device__ __forceinline__ float4 from_h4(uint2 u) {
    __half2 a = *reinterpret_cast<__half2*>(&u.x);
    __half2 b = *reinterpret_cast<__half2*>(&u.y);
    float2 f0 = __half22float2(a);
    float2 f1 = __half22float2(b);
    return make_float4(f0.x, f0.y, f1.x, f1.y);
}

// ---------------- kernels ----------------

__global__ void __launch_bounds__(256) k_deg_init(int N) {
    int i = blockIdx.x * 256 + threadIdx.x;
    if (i < N) g_dinv[i] = 1.0f;                  // self-loop
}

// Normalize edge_index (int64 OR int32, runtime-detected) + degree count at dst.
__global__ void __launch_bounds__(256) k_convert(const void* __restrict__ ei, int E) {
    long i = (long)blockIdx.x * 256 + threadIdx.x;
    if (i >= E) return;
    const unsigned long long* p64 = (const unsigned long long*)ei;
    bool is64 = true;
#pragma unroll
    for (int j = 0; j < 8; j++) is64 &= (p64[j] < (unsigned long long)N_MAX);
    int s, d;
    if (is64) {
        s = (int)p64[i];
        d = (int)p64[(long)E + i];
    } else {
        const int* p32 = (const int*)ei;
        s = p32[i];
        d = p32[(long)E + i];
    }
    g_src[i] = s;
    g_dst[i] = d;
    atomicAdd(&g_dinv[d], 1.0f);
}

// dinv = rsqrt(deg); agg1[i] = x[i]/deg[i] (fp32-exact self-loop); g_xh = fp16(x).
__global__ void __launch_bounds__(256) k_selfinit(const float* __restrict__ x, int N) {
    int tid = threadIdx.x;
    int l = tid & 15;
    int row = blockIdx.x * 16 + (tid >> 4);
    if (row >= N) return;
    float dv = rsqrtf(g_dinv[row]);
    if (l == 0) g_dinv[row] = dv;
    float w = dv * dv;
    float4 v = __ldg((const float4*)x + (size_t)row * 16 + l);
    g_xh[(size_t)row * 16 + l] = to_h4(v);
    v.x *= w; v.y *= w; v.z *= w; v.w *= w;
    ((float4*)g_agg1)[(size_t)row * 16 + l] = v;
}

// Edge aggregation: 4 consecutive edges per 16-lane group, fp16 gathers (128 B/edge),
// fp32 scale + fp32 red.v4 scatter.
__global__ void __launch_bounds__(256) k_agg(int E, int which) {
    int tid = threadIdx.x;
    int l = tid & 15;
    long g = (long)blockIdx.x * 16 + (tid >> 4);
    long e0 = g * 4;
    if (e0 >= E) return;
    const uint2* fh = which ? g_p2h : g_xh;
    float*       ob = which ? g_agg2 : g_agg1;
    int4 ss = *(const int4*)(g_src + e0);   // padded arrays: safe at tail
    int4 dd = *(const int4*)(g_dst + e0);
    if (e0 + 4 <= E) {
        float ws0 = g_dinv[ss.x], ws1 = g_dinv[ss.y];
        float ws2 = g_dinv[ss.z], ws3 = g_dinv[ss.w];
        float wd0 = g_dinv[dd.x], wd1 = g_dinv[dd.y];
        float wd2 = g_dinv[dd.z], wd3 = g_dinv[dd.w];
        uint2 r0 = __ldg(fh + (size_t)ss.x * 16 + l);
        uint2 r1 = __ldg(fh + (size_t)ss.y * 16 + l);
        uint2 r2 = __ldg(fh + (size_t)ss.z * 16 + l);
        uint2 r3 = __ldg(fh + (size_t)ss.w * 16 + l);
        float4 v0 = from_h4(r0), v1 = from_h4(r1);
        float4 v2 = from_h4(r2), v3 = from_h4(r3);
        float w0 = ws0 * wd0, w1 = ws1 * wd1, w2 = ws2 * wd2, w3 = ws3 * wd3;
        v0.x *= w0; v0.y *= w0; v0.z *= w0; v0.w *= w0;
        v1.x *= w1; v1.y *= w1; v1.z *= w1; v1.w *= w1;
        v2.x *= w2; v2.y *= w2; v2.z *= w2; v2.w *= w2;
        v3.x *= w3; v3.y *= w3; v3.z *= w3; v3.w *= w3;
        red_add_v4(ob + (size_t)dd.x * 64 + l * 4, v0);
        red_add_v4(ob + (size_t)dd.y * 64 + l * 4, v1);
        red_add_v4(ob + (size_t)dd.z * 64 + l * 4, v2);
        red_add_v4(ob + (size_t)dd.w * 64 + l * 4, v3);
    } else {
        int rem = (int)(E - e0);
        int sa[4] = {ss.x, ss.y, ss.z, ss.w};
        int da[4] = {dd.x, dd.y, dd.z, dd.w};
#pragma unroll 1
        for (int k = 0; k < rem; k++) {
            int s = sa[k], d = da[k];
            float w = g_dinv[s] * g_dinv[d];
            float4 v = from_h4(__ldg(fh + (size_t)s * 16 + l));
            v.x *= w; v.y *= w; v.z *= w; v.w *= w;
            red_add_v4(ob + (size_t)d * 64 + l * 4, v);
        }
    }
}

// h1 = relu(agg1 @ W1 + b1)   [N,64]x[64,128]
__global__ void __launch_bounds__(256) k_gemm1(const float* __restrict__ W,
                                               const float* __restrict__ b, int N) {
    __shared__ float Ws[64 * 128];
    int tid = threadIdx.x;
    {
        const float4* wv = (const float4*)W;
        float4* sv = (float4*)Ws;
#pragma unroll
        for (int i = 0; i < 8; i++) sv[tid + 256 * i] = wv[tid + 256 * i];
    }
    __syncthreads();
    int tx = tid & 15, ty = tid >> 4;
    int c0 = tx * 8;
    long rowbase = (long)blockIdx.x * 64 + ty * 4;

    long rowc[4];
#pragma unroll
    for (int r = 0; r < 4; r++) {
        long rr = rowbase + r;
        rowc[r] = (rr < N) ? rr : (long)(N - 1);
    }
    unsigned long long acc[4][4];
    {
        float4 b0 = __ldg((const float4*)(b + c0));
        float4 b1 = __ldg((const float4*)(b + c0 + 4));
#pragma unroll
        for (int r = 0; r < 4; r++) {
            acc[r][0] = pack2(b0.x, b0.y);
            acc[r][1] = pack2(b0.z, b0.w);
            acc[r][2] = pack2(b1.x, b1.y);
            acc[r][3] = pack2(b1.z, b1.w);
        }
    }
#pragma unroll 4
    for (int k0 = 0; k0 < 64; k0 += 4) {
        float a_[4][4];
#pragma unroll
        for (int r = 0; r < 4; r++)
            *(float4*)a_[r] = __ldg((const float4*)(g_agg1 + (size_t)rowc[r] * 64 + k0));
#pragma unroll
        for (int kk = 0; kk < 4; kk++) {
            int k = k0 + kk;
            ulonglong2 wa = *(const ulonglong2*)&Ws[k * 128 + c0];
            ulonglong2 wb = *(const ulonglong2*)&Ws[k * 128 + c0 + 4];
#pragma unroll
            for (int r = 0; r < 4; r++) {
                unsigned long long Ar = pack2(a_[r][kk], a_[r][kk]);
                acc[r][0] = fma2(Ar, wa.x, acc[r][0]);
                acc[r][1] = fma2(Ar, wa.y, acc[r][1]);
                acc[r][2] = fma2(Ar, wb.x, acc[r][2]);
                acc[r][3] = fma2(Ar, wb.y, acc[r][3]);
            }
        }
    }
#pragma unroll
    for (int r = 0; r < 4; r++) {
        long row = rowbase + r;
        if (row >= N) break;
        float o[8];
        unpack2(acc[r][0], o[0], o[1]);
        unpack2(acc[r][1], o[2], o[3]);
        unpack2(acc[r][2], o[4], o[5]);
        unpack2(acc[r][3], o[6], o[7]);
#pragma unroll
        for (int j = 0; j < 8; j++) o[j] = fmaxf(o[j], 0.f);
        float* dst = g_h1 + (size_t)row * 128 + c0;
        *(float4*)dst       = make_float4(o[0], o[1], o[2], o[3]);
        *(float4*)(dst + 4) = make_float4(o[4], o[5], o[6], o[7]);
    }
}

// p2 = h1 @ W2 (no bias); writes p2 as fp16 mirror + fp32 self-loop init of agg2.
__global__ void __launch_bounds__(256) k_gemm2(const float* __restrict__ W, int N) {
    __shared__ float Ws[128 * 64];
    int tid = threadIdx.x;
    {
        const float4* wv = (const float4*)W;
        float4* sv = (float4*)Ws;
#pragma unroll
        for (int i = 0; i < 8; i++) sv[tid + 256 * i] = wv[tid + 256 * i];
    }
    __syncthreads();
    int tx = tid & 15, ty = tid >> 4;
    int c0 = tx * 4;
    long rowbase = (long)blockIdx.x * 64 + ty * 4;

    long rowc[4];
#pragma unroll
    for (int r = 0; r < 4; r++) {
        long rr = rowbase + r;
        rowc[r] = (rr < N) ? rr : (long)(N - 1);
    }
    unsigned long long acc[4][2];
#pragma unroll
    for (int r = 0; r < 4; r++) { acc[r][0] = 0ull; acc[r][1] = 0ull; }

#pragma unroll 4
    for (int k0 = 0; k0 < 128; k0 += 4) {
        float a_[4][4];
#pragma unroll
        for (int r = 0; r < 4; r++)
            *(float4*)a_[r] = __ldg((const float4*)(g_h1 + (size_t)rowc[r] * 128 + k0));
#pragma unroll
        for (int kk = 0; kk < 4; kk++) {
            int k = k0 + kk;
            ulonglong2 wv = *(const ulonglong2*)&Ws[k * 64 + c0];
#pragma unroll
            for (int r = 0; r < 4; r++) {
                unsigned long long Ar = pack2(a_[r][kk], a_[r][kk]);
                acc[r][0] = fma2(Ar, wv.x, acc[r][0]);
                acc[r][1] = fma2(Ar, wv.y, acc[r][1]);
            }
        }
    }
#pragma unroll
    for (int r = 0; r < 4; r++) {
        long row = rowbase + r;
        if (row >= N) break;
        float o[4];
        unpack2(acc[r][0], o[0], o[1]);
        unpack2(acc[r][1], o[2], o[3]);
        float4 po = make_float4(o[0], o[1], o[2], o[3]);
        g_p2h[(size_t)row * 16 + (c0 >> 2)] = to_h4(po);   // fp16 mirror for gathers
        float dv = g_dinv[row];
        float w = dv * dv;
        po.x *= w; po.y *= w; po.z *= w; po.w *= w;
        *(float4*)(g_agg2 + (size_t)row * 64 + c0) = po;   // fp32-exact self term
    }
}

// per-node readout: pAB[n] = (dot(relu(agg2+b2), Wc[:64]), dot(relu(agg2+b2), Wc[64:]))
__global__ void __launch_bounds__(256) k_nodescore(const float* __restrict__ Wc,
                                                   const float* __restrict__ b2, int N) {
    int tid = threadIdx.x;
    int l = tid & 15;
    int row = blockIdx.x * 16 + (tid >> 4);
    if (row >= N) return;
    float4 wa = __ldg((const float4*)Wc + l);
    float4 wb = __ldg((const float4*)Wc + 16 + l);
    float4 b4 = __ldg((const float4*)b2 + l);
    float4 v = ((const float4*)g_agg2)[(size_t)row * 16 + l];
    v.x = fmaxf(v.x + b4.x, 0.f); v.y = fmaxf(v.y + b4.y, 0.f);
    v.z = fmaxf(v.z + b4.z, 0.f); v.w = fmaxf(v.w + b4.w, 0.f);
    float pa = v.x * wa.x + v.y * wa.y + v.z * wa.z + v.w * wa.w;
    float pb = v.x * wb.x + v.y * wb.y + v.z * wb.z + v.w * wb.w;
#pragma unroll
    for (int o = 8; o >= 1; o >>= 1) {
        pa += __shfl_down_sync(0xffffffffu, pa, o, 16);
        pb += __shfl_down_sync(0xffffffffu, pb, o, 16);
    }
    if (l == 0) g_pAB[row] = make_float2(pa, pb);
}

__global__ void __launch_bounds__(256) k_edge(const float* __restrict__ bcp,
                                              float* __restrict__ out, int E) {
    long e = (long)blockIdx.x * 256 + threadIdx.x;
    if (e >= E) return;
    int s = g_src[e], d = g_dst[e];
    float2 ps = __ldg(&g_pAB[s]);
    float2 pd = __ldg(&g_pAB[d]);
    float z = ps.x + pd.y + __ldg(bcp);
    out[e] = 1.0f / (1.0f + __expf(-z));
}

// ---------------- launcher ----------------
extern "C" void kernel_launch(void* const* d_in, const int* in_sizes, int n_in,
                              void* d_out, int out_size) {
    const float* x  = (const float*)d_in[0];
    const void*  ei = d_in[1];
    const float* W1 = (const float*)d_in[2];
    const float* b1 = (const float*)d_in[3];
    const float* W2 = (const float*)d_in[4];
    const float* b2 = (const float*)d_in[5];
    const float* Wc = (const float*)d_in[6];
    const float* bc = (const float*)d_in[7];
    float* out = (float*)d_out;

    int N = in_sizes[0] / 64;
    int E = in_sizes[1] / 2;
    if (N > N_MAX) N = N_MAX;
    if (E > E_MAX) E = E_MAX;

    long groups = ((long)E + 3) / 4;
    int  eb4  = (int)((groups + 15) / 16);   // 16 groups (64 edges) per block
    int  nb16 = (N + 15) / 16;
    int  gb   = (N + 63) / 64;
    int  ebs  = (E + 255) / 256;

    k_deg_init <<<(N + 255) / 256, 256>>>(N);
    k_convert  <<<ebs, 256>>>(ei, E);
    k_selfinit <<<nb16, 256>>>(x, N);
    k_agg      <<<eb4, 256>>>(E, 0);
    k_gemm1    <<<gb, 256>>>(W1, b1, N);
    k_gemm2    <<<gb, 256>>>(W2, N);
    k_agg      <<<eb4, 256>>>(E, 1);
    k_nodescore<<<nb16, 256>>>(Wc, b2, N);
    k_edge     <<<ebs, 256>>>(bc, out, E);
}

// round 12
// speedup vs baseline: 2.4529x; 1.4520x over previous
#include <cuda_runtime.h>
#include <cuda_fp16.h>
#include <cuda_bf16.h>

#define N_MAX 100000
#define E_MAX 1000000

// ---------------- device scratch ----------------
__device__ float  g_dinv[N_MAX];
__device__ int    g_src[E_MAX + 4];   // +4 pad: int4 index loads at the tail
__device__ int    g_dst[E_MAX + 4];
__device__ float  g_agg1[(size_t)N_MAX * 64];
__device__ __half g_h1h [(size_t)N_MAX * 128];  // h1 stored fp16 (feeds fp16 GEMM2)
__device__ float  g_agg2[(size_t)N_MAX * 64];
__device__ uint2  g_xh  [(size_t)N_MAX * 16];   // x  as fp16 (64 feats = 16 uint2)
__device__ uint2  g_p2h [(size_t)N_MAX * 16];   // p2 as fp16
__device__ float2 g_pAB [N_MAX];

// ---------------- helpers ----------------
__device__ __forceinline__ void red_add_v4(float* p, float4 v) {
    asm volatile("red.global.add.v4.f32 [%0], {%1, %2, %3, %4};"
                 :: "l"(p), "f"(v.x), "f"(v.y), "f"(v.z), "f"(v.w)
                 : "memory");
}
__device__ __forceinline__ uint2 to_h4(float4 v) {
    __half2 a = __floats2half2_rn(v.x, v.y);
    __half2 b = __floats2half2_rn(v.z, v.w);
    uint2 u;
    u.x = *reinterpret_cast<unsigned int*>(&a);
    u.y = *reinterpret_cast<unsigned int*>(&b);
    return u;
}
__device__ __forceinline__ float4 from_h4(uint2 u) {
    __half2 a = *reinterpret_cast<__half2*>(&u.x);
    __half2 b = *reinterpret_cast<__half2*>(&u.y);
    float2 f0 = __half22float2(a);
    float2 f1 = __half22float2(b);
    return make_float4(f0.x, f0.y, f1.x, f1.y);
}
__device__ __forceinline__ unsigned h2u(float2 f) {
    __half2 h = __floats2half2_rn(f.x, f.y);
    return *reinterpret_cast<unsigned*>(&h);
}
__device__ __forceinline__ void mma16816(float& c0, float& c1, float& c2, float& c3,
                                         unsigned a0, unsigned a1, unsigned a2, unsigned a3,
                                         unsigned b0, unsigned b1) {
    asm volatile(
        "mma.sync.aligned.m16n8k16.row.col.f32.f16.f16.f32 "
        "{%0,%1,%2,%3},{%4,%5,%6,%7},{%8,%9},{%0,%1,%2,%3};"
        : "+f"(c0), "+f"(c1), "+f"(c2), "+f"(c3)
        : "r"(a0), "r"(a1), "r"(a2), "r"(a3), "r"(b0), "r"(b1));
}

// ---------------- kernels ----------------

__global__ void __launch_bounds__(256) k_deg_init(int N) {
    int i = blockIdx.x * 256 + threadIdx.x;
    if (i < N) g_dinv[i] = 1.0f;                  // self-loop
}

// Normalize edge_index (int64 OR int32, runtime-detected) + degree count at dst.
__global__ void __launch_bounds__(256) k_convert(const void* __restrict__ ei, int E) {
    long i = (long)blockIdx.x * 256 + threadIdx.x;
    if (i >= E) return;
    const unsigned long long* p64 = (const unsigned long long*)ei;
    bool is64 = true;
#pragma unroll
    for (int j = 0; j < 8; j++) is64 &= (p64[j] < (unsigned long long)N_MAX);
    int s, d;
    if (is64) {
        s = (int)p64[i];
        d = (int)p64[(long)E + i];
    } else {
        const int* p32 = (const int*)ei;
        s = p32[i];
        d = p32[(long)E + i];
    }
    g_src[i] = s;
    g_dst[i] = d;
    atomicAdd(&g_dinv[d], 1.0f);
}

// dinv = rsqrt(deg); agg1[i] = x[i]/deg[i] (fp32-exact self-loop); g_xh = fp16(x).
__global__ void __launch_bounds__(256) k_selfinit(const float* __restrict__ x, int N) {
    int tid = threadIdx.x;
    int l = tid & 15;
    int row = blockIdx.x * 16 + (tid >> 4);
    if (row >= N) return;
    float dv = rsqrtf(g_dinv[row]);
    if (l == 0) g_dinv[row] = dv;
    float w = dv * dv;
    float4 v = __ldg((const float4*)x + (size_t)row * 16 + l);
    g_xh[(size_t)row * 16 + l] = to_h4(v);
    v.x *= w; v.y *= w; v.z *= w; v.w *= w;
    ((float4*)g_agg1)[(size_t)row * 16 + l] = v;
}

// Edge aggregation: 4 consecutive edges per 16-lane group, fp16 gathers,
// fp32 scale + fp32 red.v4 scatter.
__global__ void __launch_bounds__(256) k_agg(int E, int which) {
    int tid = threadIdx.x;
    int l = tid & 15;
    long g = (long)blockIdx.x * 16 + (tid >> 4);
    long e0 = g * 4;
    if (e0 >= E) return;
    const uint2* fh = which ? g_p2h : g_xh;
    float*       ob = which ? g_agg2 : g_agg1;
    int4 ss = *(const int4*)(g_src + e0);   // padded arrays: safe at tail
    int4 dd = *(const int4*)(g_dst + e0);
    if (e0 + 4 <= E) {
        float ws0 = g_dinv[ss.x], ws1 = g_dinv[ss.y];
        float ws2 = g_dinv[ss.z], ws3 = g_dinv[ss.w];
        float wd0 = g_dinv[dd.x], wd1 = g_dinv[dd.y];
        float wd2 = g_dinv[dd.z], wd3 = g_dinv[dd.w];
        uint2 r0 = __ldg(fh + (size_t)ss.x * 16 + l);
        uint2 r1 = __ldg(fh + (size_t)ss.y * 16 + l);
        uint2 r2 = __ldg(fh + (size_t)ss.z * 16 + l);
        uint2 r3 = __ldg(fh + (size_t)ss.w * 16 + l);
        float4 v0 = from_h4(r0), v1 = from_h4(r1);
        float4 v2 = from_h4(r2), v3 = from_h4(r3);
        float w0 = ws0 * wd0, w1 = ws1 * wd1, w2 = ws2 * wd2, w3 = ws3 * wd3;
        v0.x *= w0; v0.y *= w0; v0.z *= w0; v0.w *= w0;
        v1.x *= w1; v1.y *= w1; v1.z *= w1; v1.w *= w1;
        v2.x *= w2; v2.y *= w2; v2.z *= w2; v2.w *= w2;
        v3.x *= w3; v3.y *= w3; v3.z *= w3; v3.w *= w3;
        red_add_v4(ob + (size_t)dd.x * 64 + l * 4, v0);
        red_add_v4(ob + (size_t)dd.y * 64 + l * 4, v1);
        red_add_v4(ob + (size_t)dd.z * 64 + l * 4, v2);
        red_add_v4(ob + (size_t)dd.w * 64 + l * 4, v3);
    } else {
        int rem = (int)(E - e0);
        int sa[4] = {ss.x, ss.y, ss.z, ss.w};
        int da[4] = {dd.x, dd.y, dd.z, dd.w};
#pragma unroll 1
        for (int k = 0; k < rem; k++) {
            int s = sa[k], d = da[k];
            float w = g_dinv[s] * g_dinv[d];
            float4 v = from_h4(__ldg(fh + (size_t)s * 16 + l));
            v.x *= w; v.y *= w; v.z *= w; v.w *= w;
            red_add_v4(ob + (size_t)d * 64 + l * 4, v);
        }
    }
}

// h1 = relu(agg1 @ W1 + b1) via HMMA, stored fp16.  [N,64]x[64,128]
// 8 warps x 16 rows = 128 rows/block. W1^T staged fp16 in padded smem.
__global__ void __launch_bounds__(256) k_gemm1(const float* __restrict__ W,
                                               const float* __restrict__ b, int N) {
    __shared__ __half WT[128][72];   // [n][k], +8 halves pad -> conflict-free
    __shared__ float bs[128];
    int tid = threadIdx.x;
    for (int i = tid; i < 64 * 128; i += 256) {
        int k = i >> 7, n = i & 127;
        WT[n][k] = __float2half(W[i]);
    }
    if (tid < 128) bs[tid] = b[tid];
    __syncthreads();
    int warp = tid >> 5, lane = tid & 31;
    int g = lane >> 2, t = lane & 3;
    long row0 = (long)blockIdx.x * 128 + warp * 16;
    long r0 = row0 + g, r1 = row0 + g + 8;
    long r0c = (r0 < N) ? r0 : (long)(N - 1);
    long r1c = (r1 < N) ? r1 : (long)(N - 1);
    const float* A0 = g_agg1 + r0c * 64;
    const float* A1 = g_agg1 + r1c * 64;
    unsigned a[4][4];
#pragma unroll
    for (int ks = 0; ks < 4; ks++) {
        int c0 = ks * 16 + t * 2;
        a[ks][0] = h2u(*(const float2*)(A0 + c0));
        a[ks][1] = h2u(*(const float2*)(A1 + c0));
        a[ks][2] = h2u(*(const float2*)(A0 + c0 + 8));
        a[ks][3] = h2u(*(const float2*)(A1 + c0 + 8));
    }
#pragma unroll
    for (int nb = 0; nb < 16; nb++) {
        int ncol = nb * 8 + t * 2;
        float c0 = bs[ncol], c1 = bs[ncol + 1];
        float c2 = c0, c3 = c1;
#pragma unroll
        for (int ks = 0; ks < 4; ks++) {
            unsigned b0 = *(const unsigned*)&WT[nb * 8 + g][ks * 16 + t * 2];
            unsigned b1 = *(const unsigned*)&WT[nb * 8 + g][ks * 16 + t * 2 + 8];
            mma16816(c0, c1, c2, c3,
                     a[ks][0], a[ks][1], a[ks][2], a[ks][3], b0, b1);
        }
        __half2 h0 = __floats2half2_rn(fmaxf(c0, 0.f), fmaxf(c1, 0.f));
        __half2 h1 = __floats2half2_rn(fmaxf(c2, 0.f), fmaxf(c3, 0.f));
        if (r0 < N) *(unsigned*)&g_h1h[r0 * 128 + ncol] = *reinterpret_cast<unsigned*>(&h0);
        if (r1 < N) *(unsigned*)&g_h1h[r1 * 128 + ncol] = *reinterpret_cast<unsigned*>(&h1);
    }
}

// p2 = h1 @ W2 via HMMA (no bias). Writes fp16 p2 mirror + fp32 agg2 self-init.
// [N,128]x[128,64]
__global__ void __launch_bounds__(256) k_gemm2(const float* __restrict__ W, int N) {
    __shared__ __half WT[64][136];   // [n][k], +8 halves pad
    int tid = threadIdx.x;
    for (int i = tid; i < 128 * 64; i += 256) {
        int k = i >> 6, n = i & 63;
        WT[n][k] = __float2half(W[i]);
    }
    __syncthreads();
    int warp = tid >> 5, lane = tid & 31;
    int g = lane >> 2, t = lane & 3;
    long row0 = (long)blockIdx.x * 128 + warp * 16;
    long r0 = row0 + g, r1 = row0 + g + 8;
    long r0c = (r0 < N) ? r0 : (long)(N - 1);
    long r1c = (r1 < N) ? r1 : (long)(N - 1);
    const __half* A0 = g_h1h + r0c * 128;
    const __half* A1 = g_h1h + r1c * 128;
    unsigned a[8][4];
#pragma unroll
    for (int ks = 0; ks < 8; ks++) {
        int c0 = ks * 16 + t * 2;
        a[ks][0] = *(const unsigned*)(A0 + c0);
        a[ks][1] = *(const unsigned*)(A1 + c0);
        a[ks][2] = *(const unsigned*)(A0 + c0 + 8);
        a[ks][3] = *(const unsigned*)(A1 + c0 + 8);
    }
    float dv0 = g_dinv[r0c], dv1 = g_dinv[r1c];
    float w0 = dv0 * dv0, w1 = dv1 * dv1;
    __half* p2h = (__half*)g_p2h;
#pragma unroll
    for (int nb = 0; nb < 8; nb++) {
        int ncol = nb * 8 + t * 2;
        float c0 = 0.f, c1 = 0.f, c2 = 0.f, c3 = 0.f;
#pragma unroll
        for (int ks = 0; ks < 8; ks++) {
            unsigned b0 = *(const unsigned*)&WT[nb * 8 + g][ks * 16 + t * 2];
            unsigned b1 = *(const unsigned*)&WT[nb * 8 + g][ks * 16 + t * 2 + 8];
            mma16816(c0, c1, c2, c3,
                     a[ks][0], a[ks][1], a[ks][2], a[ks][3], b0, b1);
        }
        if (r0 < N) {
            __half2 h0 = __floats2half2_rn(c0, c1);
            *(unsigned*)&p2h[r0 * 64 + ncol] = *reinterpret_cast<unsigned*>(&h0);
            *(float2*)&g_agg2[r0 * 64 + ncol] = make_float2(c0 * w0, c1 * w0);
        }
        if (r1 < N) {
            __half2 h1 = __floats2half2_rn(c2, c3);
            *(unsigned*)&p2h[r1 * 64 + ncol] = *reinterpret_cast<unsigned*>(&h1);
            *(float2*)&g_agg2[r1 * 64 + ncol] = make_float2(c2 * w1, c3 * w1);
        }
    }
}

// per-node readout: pAB[n] = (dot(relu(agg2+b2), Wc[:64]), dot(relu(agg2+b2), Wc[64:]))
__global__ void __launch_bounds__(256) k_nodescore(const float* __restrict__ Wc,
                                                   const float* __restrict__ b2, int N) {
    int tid = threadIdx.x;
    int l = tid & 15;
    int row = blockIdx.x * 16 + (tid >> 4);
    if (row >= N) return;
    float4 wa = __ldg((const float4*)Wc + l);
    float4 wb = __ldg((const float4*)Wc + 16 + l);
    float4 b4 = __ldg((const float4*)b2 + l);
    float4 v = ((const float4*)g_agg2)[(size_t)row * 16 + l];
    v.x = fmaxf(v.x + b4.x, 0.f); v.y = fmaxf(v.y + b4.y, 0.f);
    v.z = fmaxf(v.z + b4.z, 0.f); v.w = fmaxf(v.w + b4.w, 0.f);
    float pa = v.x * wa.x + v.y * wa.y + v.z * wa.z + v.w * wa.w;
    float pb = v.x * wb.x + v.y * wb.y + v.z * wb.z + v.w * wb.w;
#pragma unroll
    for (int o = 8; o >= 1; o >>= 1) {
        pa += __shfl_down_sync(0xffffffffu, pa, o, 16);
        pb += __shfl_down_sync(0xffffffffu, pb, o, 16);
    }
    if (l == 0) g_pAB[row] = make_float2(pa, pb);
}

__global__ void __launch_bounds__(256) k_edge(const float* __restrict__ bcp,
                                              float* __restrict__ out, int E) {
    long e = (long)blockIdx.x * 256 + threadIdx.x;
    if (e >= E) return;
    int s = g_src[e], d = g_dst[e];
    float2 ps = __ldg(&g_pAB[s]);
    float2 pd = __ldg(&g_pAB[d]);
    float z = ps.x + pd.y + __ldg(bcp);
    out[e] = 1.0f / (1.0f + __expf(-z));
}

// ---------------- launcher ----------------
extern "C" void kernel_launch(void* const* d_in, const int* in_sizes, int n_in,
                              void* d_out, int out_size) {
    const float* x  = (const float*)d_in[0];
    const void*  ei = d_in[1];
    const float* W1 = (const float*)d_in[2];
    const float* b1 = (const float*)d_in[3];
    const float* W2 = (const float*)d_in[4];
    const float* b2 = (const float*)d_in[5];
    const float* Wc = (const float*)d_in[6];
    const float* bc = (const float*)d_in[7];
    float* out = (float*)d_out;

    int N = in_sizes[0] / 64;
    int E = in_sizes[1] / 2;
    if (N > N_MAX) N = N_MAX;
    if (E > E_MAX) E = E_MAX;

    long groups = ((long)E + 3) / 4;
    int  eb4  = (int)((groups + 15) / 16);   // 16 groups (64 edges) per block
    int  nb16 = (N + 15) / 16;
    int  gb   = (N + 127) / 128;
    int  ebs  = (E + 255) / 256;

    k_deg_init <<<(N + 255) / 256, 256>>>(N);
    k_convert  <<<ebs, 256>>>(ei, E);
    k_selfinit <<<nb16, 256>>>(x, N);
    k_agg      <<<eb4, 256>>>(E, 0);
    k_gemm1    <<<gb, 256>>>(W1, b1, N);
    k_gemm2    <<<gb, 256>>>(W2, N);
    k_agg      <<<eb4, 256>>>(E, 1);
    k_nodescore<<<nb16, 256>>>(Wc, b2, N);
    k_edge     <<<ebs, 256>>>(bc, out, E);
}

// round 13
// speedup vs baseline: 3.0940x; 1.2614x over previous
#include <cuda_runtime.h>
#include <cuda_fp16.h>
#include <cuda_bf16.h>

#define N_MAX 100000
#define E_MAX 1000000

// ---------------- device scratch ----------------
__device__ float  g_dinv[N_MAX];
__device__ int    g_src[E_MAX + 4];   // +4 pad: int4 index loads at the tail
__device__ int    g_dst[E_MAX + 4];
__device__ uint4  g_agg1h[(size_t)N_MAX * 8];   // agg1 fp16: 64 halves/row
__device__ uint4  g_agg2h[(size_t)N_MAX * 8];   // agg2 fp16
__device__ uint4  g_xq  [(size_t)N_MAX * 8];    // x  fp16 rows
__device__ uint4  g_p2q [(size_t)N_MAX * 8];    // p2 fp16 rows
__device__ __half g_h1h [(size_t)N_MAX * 128];  // h1 fp16 (feeds GEMM2)
__device__ float2 g_pAB [N_MAX];

// ---------------- helpers ----------------
__device__ __forceinline__ void red_add_v4h(__half* p, uint4 v) {
    asm volatile("red.global.add.noftz.v4.f16x2 [%0], {%1, %2, %3, %4};"
                 :: "l"(p), "r"(v.x), "r"(v.y), "r"(v.z), "r"(v.w)
                 : "memory");
}
__device__ __forceinline__ uint4 hscale(uint4 r, float w) {
    __half2 W = __float2half2_rn(w);
    __half2* h = reinterpret_cast<__half2*>(&r);
    h[0] = __hmul2(h[0], W); h[1] = __hmul2(h[1], W);
    h[2] = __hmul2(h[2], W); h[3] = __hmul2(h[3], W);
    return r;
}
__device__ __forceinline__ uint2 to_h4(float4 v) {
    __half2 a = __floats2half2_rn(v.x, v.y);
    __half2 b = __floats2half2_rn(v.z, v.w);
    uint2 u;
    u.x = *reinterpret_cast<unsigned int*>(&a);
    u.y = *reinterpret_cast<unsigned int*>(&b);
    return u;
}
__device__ __forceinline__ float4 from_h4(uint2 u) {
    __half2 a = *reinterpret_cast<__half2*>(&u.x);
    __half2 b = *reinterpret_cast<__half2*>(&u.y);
    float2 f0 = __half22float2(a);
    float2 f1 = __half22float2(b);
    return make_float4(f0.x, f0.y, f1.x, f1.y);
}
__device__ __forceinline__ void mma16816(float& c0, float& c1, float& c2, float& c3,
                                         unsigned a0, unsigned a1, unsigned a2, unsigned a3,
                                         unsigned b0, unsigned b1) {
    asm volatile(
        "mma.sync.aligned.m16n8k16.row.col.f32.f16.f16.f32 "
        "{%0,%1,%2,%3},{%4,%5,%6,%7},{%8,%9},{%0,%1,%2,%3};"
        : "+f"(c0), "+f"(c1), "+f"(c2), "+f"(c3)
        : "r"(a0), "r"(a1), "r"(a2), "r"(a3), "r"(b0), "r"(b1));
}

// ---------------- kernels ----------------

__global__ void __launch_bounds__(256) k_deg_init(int N) {
    int i = blockIdx.x * 256 + threadIdx.x;
    if (i < N) g_dinv[i] = 1.0f;                  // self-loop
}

// Normalize edge_index (int64 OR int32, runtime-detected) + degree count at dst.
__global__ void __launch_bounds__(256) k_convert(const void* __restrict__ ei, int E) {
    long i = (long)blockIdx.x * 256 + threadIdx.x;
    if (i >= E) return;
    const unsigned long long* p64 = (const unsigned long long*)ei;
    bool is64 = true;
#pragma unroll
    for (int j = 0; j < 8; j++) is64 &= (p64[j] < (unsigned long long)N_MAX);
    int s, d;
    if (is64) {
        s = (int)p64[i];
        d = (int)p64[(long)E + i];
    } else {
        const int* p32 = (const int*)ei;
        s = p32[i];
        d = p32[(long)E + i];
    }
    g_src[i] = s;
    g_dst[i] = d;
    atomicAdd(&g_dinv[d], 1.0f);
}

// dinv = rsqrt(deg); g_xq = fp16(x); agg1 init = fp16(x/deg) (self-loop term).
__global__ void __launch_bounds__(256) k_selfinit(const float* __restrict__ x, int N) {
    int tid = threadIdx.x;
    int l = tid & 15;
    int row = blockIdx.x * 16 + (tid >> 4);
    if (row >= N) return;
    float dv = rsqrtf(g_dinv[row]);
    if (l == 0) g_dinv[row] = dv;
    float w = dv * dv;
    float4 v = __ldg((const float4*)x + (size_t)row * 16 + l);
    ((uint2*)g_xq)[(size_t)row * 16 + l] = to_h4(v);
    v.x *= w; v.y *= w; v.z *= w; v.w *= w;
    ((uint2*)g_agg1h)[(size_t)row * 16 + l] = to_h4(v);
}

// Edge aggregation: 8 lanes per edge, 4 edges per group.
// fp16 gather (uint4 = 8 halves/lane), half2 scale, red.v4.f16x2 scatter.
__global__ void __launch_bounds__(256) k_agg(int E, int which) {
    int tid = threadIdx.x;
    int l = tid & 7;
    long g = (long)blockIdx.x * 32 + (tid >> 3);
    long e0 = g * 4;
    if (e0 >= E) return;
    const uint4* fh = which ? g_p2q : g_xq;
    __half*      ob = which ? (__half*)g_agg2h : (__half*)g_agg1h;
    int4 ss = *(const int4*)(g_src + e0);   // padded arrays: safe at tail
    int4 dd = *(const int4*)(g_dst + e0);
    if (e0 + 4 <= E) {
        float w0 = g_dinv[ss.x] * g_dinv[dd.x];
        float w1 = g_dinv[ss.y] * g_dinv[dd.y];
        float w2 = g_dinv[ss.z] * g_dinv[dd.z];
        float w3 = g_dinv[ss.w] * g_dinv[dd.w];
        uint4 r0 = __ldg(fh + (size_t)ss.x * 8 + l);
        uint4 r1 = __ldg(fh + (size_t)ss.y * 8 + l);
        uint4 r2 = __ldg(fh + (size_t)ss.z * 8 + l);
        uint4 r3 = __ldg(fh + (size_t)ss.w * 8 + l);
        r0 = hscale(r0, w0); r1 = hscale(r1, w1);
        r2 = hscale(r2, w2); r3 = hscale(r3, w3);
        red_add_v4h(ob + (size_t)dd.x * 64 + l * 8, r0);
        red_add_v4h(ob + (size_t)dd.y * 64 + l * 8, r1);
        red_add_v4h(ob + (size_t)dd.z * 64 + l * 8, r2);
        red_add_v4h(ob + (size_t)dd.w * 64 + l * 8, r3);
    } else {
        int rem = (int)(E - e0);
        int sa[4] = {ss.x, ss.y, ss.z, ss.w};
        int da[4] = {dd.x, dd.y, dd.z, dd.w};
#pragma unroll 1
        for (int k = 0; k < rem; k++) {
            int s = sa[k], d = da[k];
            float w = g_dinv[s] * g_dinv[d];
            uint4 r = hscale(__ldg(fh + (size_t)s * 8 + l), w);
            red_add_v4h(ob + (size_t)d * 64 + l * 8, r);
        }
    }
}

// h1 = relu(agg1 @ W1 + b1) via HMMA, A read directly as fp16.  [N,64]x[64,128]
__global__ void __launch_bounds__(256) k_gemm1(const float* __restrict__ W,
                                               const float* __restrict__ b, int N) {
    __shared__ __half WT[128][72];   // [n][k], padded -> conflict-free
    __shared__ float bs[128];
    int tid = threadIdx.x;
    for (int i = tid; i < 64 * 128; i += 256) {
        int k = i >> 7, n = i & 127;
        WT[n][k] = __float2half(W[i]);
    }
    if (tid < 128) bs[tid] = b[tid];
    __syncthreads();
    int warp = tid >> 5, lane = tid & 31;
    int g = lane >> 2, t = lane & 3;
    long row0 = (long)blockIdx.x * 128 + warp * 16;
    long r0 = row0 + g, r1 = row0 + g + 8;
    long r0c = (r0 < N) ? r0 : (long)(N - 1);
    long r1c = (r1 < N) ? r1 : (long)(N - 1);
    const __half* A0 = (const __half*)g_agg1h + r0c * 64;
    const __half* A1 = (const __half*)g_agg1h + r1c * 64;
    unsigned a[4][4];
#pragma unroll
    for (int ks = 0; ks < 4; ks++) {
        int c0 = ks * 16 + t * 2;
        a[ks][0] = *(const unsigned*)(A0 + c0);
        a[ks][1] = *(const unsigned*)(A1 + c0);
        a[ks][2] = *(const unsigned*)(A0 + c0 + 8);
        a[ks][3] = *(const unsigned*)(A1 + c0 + 8);
    }
#pragma unroll
    for (int nb = 0; nb < 16; nb++) {
        int ncol = nb * 8 + t * 2;
        float c0 = bs[ncol], c1 = bs[ncol + 1];
        float c2 = c0, c3 = c1;
#pragma unroll
        for (int ks = 0; ks < 4; ks++) {
            unsigned b0 = *(const unsigned*)&WT[nb * 8 + g][ks * 16 + t * 2];
            unsigned b1 = *(const unsigned*)&WT[nb * 8 + g][ks * 16 + t * 2 + 8];
            mma16816(c0, c1, c2, c3,
                     a[ks][0], a[ks][1], a[ks][2], a[ks][3], b0, b1);
        }
        __half2 h0 = __floats2half2_rn(fmaxf(c0, 0.f), fmaxf(c1, 0.f));
        __half2 h1 = __floats2half2_rn(fmaxf(c2, 0.f), fmaxf(c3, 0.f));
        if (r0 < N) *(unsigned*)&g_h1h[r0 * 128 + ncol] = *reinterpret_cast<unsigned*>(&h0);
        if (r1 < N) *(unsigned*)&g_h1h[r1 * 128 + ncol] = *reinterpret_cast<unsigned*>(&h1);
    }
}

// p2 = h1 @ W2 via HMMA (no bias). Writes fp16 p2 mirror + fp16 agg2 self-init.
__global__ void __launch_bounds__(256) k_gemm2(const float* __restrict__ W, int N) {
    __shared__ __half WT[64][136];   // [n][k], padded
    int tid = threadIdx.x;
    for (int i = tid; i < 128 * 64; i += 256) {
        int k = i >> 6, n = i & 63;
        WT[n][k] = __float2half(W[i]);
    }
    __syncthreads();
    int warp = tid >> 5, lane = tid & 31;
    int g = lane >> 2, t = lane & 3;
    long row0 = (long)blockIdx.x * 128 + warp * 16;
    long r0 = row0 + g, r1 = row0 + g + 8;
    long r0c = (r0 < N) ? r0 : (long)(N - 1);
    long r1c = (r1 < N) ? r1 : (long)(N - 1);
    const __half* A0 = g_h1h + r0c * 128;
    const __half* A1 = g_h1h + r1c * 128;
    unsigned a[8][4];
#pragma unroll
    for (int ks = 0; ks < 8; ks++) {
        int c0 = ks * 16 + t * 2;
        a[ks][0] = *(const unsigned*)(A0 + c0);
        a[ks][1] = *(const unsigned*)(A1 + c0);
        a[ks][2] = *(const unsigned*)(A0 + c0 + 8);
        a[ks][3] = *(const unsigned*)(A1 + c0 + 8);
    }
    float dv0 = g_dinv[r0c], dv1 = g_dinv[r1c];
    float w0 = dv0 * dv0, w1 = dv1 * dv1;
    __half* p2h  = (__half*)g_p2q;
    __half* a2h  = (__half*)g_agg2h;
#pragma unroll
    for (int nb = 0; nb < 8; nb++) {
        int ncol = nb * 8 + t * 2;
        float c0 = 0.f, c1 = 0.f, c2 = 0.f, c3 = 0.f;
#pragma unroll
        for (int ks = 0; ks < 8; ks++) {
            unsigned b0 = *(const unsigned*)&WT[nb * 8 + g][ks * 16 + t * 2];
            unsigned b1 = *(const unsigned*)&WT[nb * 8 + g][ks * 16 + t * 2 + 8];
            mma16816(c0, c1, c2, c3,
                     a[ks][0], a[ks][1], a[ks][2], a[ks][3], b0, b1);
        }
        if (r0 < N) {
            __half2 h0 = __floats2half2_rn(c0, c1);
            *(unsigned*)&p2h[r0 * 64 + ncol] = *reinterpret_cast<unsigned*>(&h0);
            __half2 s0 = __floats2half2_rn(c0 * w0, c1 * w0);
            *(unsigned*)&a2h[r0 * 64 + ncol] = *reinterpret_cast<unsigned*>(&s0);
        }
        if (r1 < N) {
            __half2 h1 = __floats2half2_rn(c2, c3);
            *(unsigned*)&p2h[r1 * 64 + ncol] = *reinterpret_cast<unsigned*>(&h1);
            __half2 s1 = __floats2half2_rn(c2 * w1, c3 * w1);
            *(unsigned*)&a2h[r1 * 64 + ncol] = *reinterpret_cast<unsigned*>(&s1);
        }
    }
}

// per-node readout: pAB[n] = (dot(relu(agg2+b2), Wc[:64]), dot(relu(agg2+b2), Wc[64:]))
__global__ void __launch_bounds__(256) k_nodescore(const float* __restrict__ Wc,
                                                   const float* __restrict__ b2, int N) {
    int tid = threadIdx.x;
    int l = tid & 15;
    int row = blockIdx.x * 16 + (tid >> 4);
    if (row >= N) return;
    float4 wa = __ldg((const float4*)Wc + l);
    float4 wb = __ldg((const float4*)Wc + 16 + l);
    float4 b4 = __ldg((const float4*)b2 + l);
    float4 v = from_h4(((const uint2*)g_agg2h)[(size_t)row * 16 + l]);
    v.x = fmaxf(v.x + b4.x, 0.f); v.y = fmaxf(v.y + b4.y, 0.f);
    v.z = fmaxf(v.z + b4.z, 0.f); v.w = fmaxf(v.w + b4.w, 0.f);
    float pa = v.x * wa.x + v.y * wa.y + v.z * wa.z + v.w * wa.w;
    float pb = v.x * wb.x + v.y * wb.y + v.z * wb.z + v.w * wb.w;
#pragma unroll
    for (int o = 8; o >= 1; o >>= 1) {
        pa += __shfl_down_sync(0xffffffffu, pa, o, 16);
        pb += __shfl_down_sync(0xffffffffu, pb, o, 16);
    }
    if (l == 0) g_pAB[row] = make_float2(pa, pb);
}

__global__ void __launch_bounds__(256) k_edge(const float* __restrict__ bcp,
                                              float* __restrict__ out, int E) {
    long e = (long)blockIdx.x * 256 + threadIdx.x;
    if (e >= E) return;
    int s = g_src[e], d = g_dst[e];
    float2 ps = __ldg(&g_pAB[s]);
    float2 pd = __ldg(&g_pAB[d]);
    float z = ps.x + pd.y + __ldg(bcp);
    out[e] = 1.0f / (1.0f + __expf(-z));
}

// ---------------- launcher ----------------
extern "C" void kernel_launch(void* const* d_in, const int* in_sizes, int n_in,
                              void* d_out, int out_size) {
    const float* x  = (const float*)d_in[0];
    const void*  ei = d_in[1];
    const float* W1 = (const float*)d_in[2];
    const float* b1 = (const float*)d_in[3];
    const float* W2 = (const float*)d_in[4];
    const float* b2 = (const float*)d_in[5];
    const float* Wc = (const float*)d_in[6];
    const float* bc = (const float*)d_in[7];
    float* out = (float*)d_out;

    int N = in_sizes[0] / 64;
    int E = in_sizes[1] / 2;
    if (N > N_MAX) N = N_MAX;
    if (E > E_MAX) E = E_MAX;

    int eb128 = (E + 127) / 128;    // 32 groups x 4 edges per block
    int nb16  = (N + 15) / 16;
    int gb    = (N + 127) / 128;
    int ebs   = (E + 255) / 256;

    k_deg_init <<<(N + 255) / 256, 256>>>(N);
    k_convert  <<<ebs, 256>>>(ei, E);
    k_selfinit <<<nb16, 256>>>(x, N);
    k_agg      <<<eb128, 256>>>(E, 0);
    k_gemm1    <<<gb, 256>>>(W1, b1, N);
    k_gemm2    <<<gb, 256>>>(W2, N);
    k_agg      <<<eb128, 256>>>(E, 1);
    k_nodescore<<<nb16, 256>>>(Wc, b2, N);
    k_edge     <<<ebs, 256>>>(bc, out, E);
}

// round 14
// speedup vs baseline: 3.4858x; 1.1266x over previous
#include <cuda_runtime.h>
#include <cuda_fp16.h>
#include <cuda_bf16.h>

#define N_MAX 100000
#define E_MAX 1000000

// ---------------- device scratch ----------------
__device__ float  g_dinv[N_MAX];
__device__ int    g_cnt[N_MAX];                 // zero at load; k_prep resets after use
__device__ int    g_src[E_MAX + 4];             // +4 pad: int4 loads at tail
__device__ int    g_dst[E_MAX + 4];
__device__ float  g_w  [E_MAX + 4];             // per-edge norm weight (pass-1 caches)
__device__ uint4  g_agg1h[(size_t)N_MAX * 8];   // agg1 fp16: 64 halves/row
__device__ uint4  g_agg2h[(size_t)N_MAX * 8];   // agg2 fp16
__device__ uint4  g_xq  [(size_t)N_MAX * 8];    // x  fp16 rows
__device__ uint4  g_p2q [(size_t)N_MAX * 8];    // p2 fp16 rows
__device__ float2 g_pAB [N_MAX];

// ---------------- helpers ----------------
__device__ __forceinline__ void red_add_v4h(__half* p, uint4 v) {
    asm volatile("red.global.add.noftz.v4.f16x2 [%0], {%1, %2, %3, %4};"
                 :: "l"(p), "r"(v.x), "r"(v.y), "r"(v.z), "r"(v.w)
                 : "memory");
}
__device__ __forceinline__ uint4 hscale(uint4 r, float w) {
    __half2 W = __float2half2_rn(w);
    __half2* h = reinterpret_cast<__half2*>(&r);
    h[0] = __hmul2(h[0], W); h[1] = __hmul2(h[1], W);
    h[2] = __hmul2(h[2], W); h[3] = __hmul2(h[3], W);
    return r;
}
__device__ __forceinline__ uint2 to_h4(float4 v) {
    __half2 a = __floats2half2_rn(v.x, v.y);
    __half2 b = __floats2half2_rn(v.z, v.w);
    uint2 u;
    u.x = *reinterpret_cast<unsigned int*>(&a);
    u.y = *reinterpret_cast<unsigned int*>(&b);
    return u;
}
__device__ __forceinline__ float4 from_h4(uint2 u) {
    __half2 a = *reinterpret_cast<__half2*>(&u.x);
    __half2 b = *reinterpret_cast<__half2*>(&u.y);
    float2 f0 = __half22float2(a);
    float2 f1 = __half22float2(b);
    return make_float4(f0.x, f0.y, f1.x, f1.y);
}
__device__ __forceinline__ unsigned h2u2(float x, float y) {
    __half2 h = __floats2half2_rn(x, y);
    return *reinterpret_cast<unsigned*>(&h);
}
__device__ __forceinline__ void mma16816(float& c0, float& c1, float& c2, float& c3,
                                         unsigned a0, unsigned a1, unsigned a2, unsigned a3,
                                         unsigned b0, unsigned b1) {
    asm volatile(
        "mma.sync.aligned.m16n8k16.row.col.f32.f16.f16.f32 "
        "{%0,%1,%2,%3},{%4,%5,%6,%7},{%8,%9},{%0,%1,%2,%3};"
        : "+f"(c0), "+f"(c1), "+f"(c2), "+f"(c3)
        : "r"(a0), "r"(a1), "r"(a2), "r"(a3), "r"(b0), "r"(b1));
}

// ---------------- kernels ----------------

// Normalize edge_index (int64 OR int32, runtime-detected) + int degree count at dst.
__global__ void __launch_bounds__(256) k_convert(const void* __restrict__ ei, int E) {
    long i = (long)blockIdx.x * 256 + threadIdx.x;
    if (i >= E) return;
    const unsigned long long* p64 = (const unsigned long long*)ei;
    bool is64 = true;
#pragma unroll
    for (int j = 0; j < 8; j++) is64 &= (p64[j] < (unsigned long long)N_MAX);
    int s, d;
    if (is64) {
        s = (int)p64[i];
        d = (int)p64[(long)E + i];
    } else {
        const int* p32 = (const int*)ei;
        s = p32[i];
        d = p32[(long)E + i];
    }
    g_src[i] = s;
    g_dst[i] = d;
    atomicAdd(&g_cnt[d], 1);
}

// dinv = rsqrt(cnt+1) (and reset cnt for next replay); g_xq = fp16(x);
// agg1 init = fp16(x/deg) (self-loop term).
__global__ void __launch_bounds__(256) k_prep(const float* __restrict__ x, int N) {
    int tid = threadIdx.x;
    int l = tid & 15;
    int row = blockIdx.x * 16 + (tid >> 4);
    if (row >= N) return;
    int cnt = g_cnt[row];
    float dv = rsqrtf((float)(cnt + 1));
    if (l == 0) { g_dinv[row] = dv; g_cnt[row] = 0; }
    float w = dv * dv;
    float4 v = __ldg((const float4*)x + (size_t)row * 16 + l);
    ((uint2*)g_xq)[(size_t)row * 16 + l] = to_h4(v);
    v.x *= w; v.y *= w; v.z *= w; v.w *= w;
    ((uint2*)g_agg1h)[(size_t)row * 16 + l] = to_h4(v);
}

// Edge aggregation: 8 lanes per edge, 4 edges per group.
// pass 0: compute w from dinv and CACHE to g_w; pass 1: broadcast-load cached w.
__global__ void __launch_bounds__(256) k_agg(int E, int which) {
    int tid = threadIdx.x;
    int l = tid & 7;
    long g = (long)blockIdx.x * 32 + (tid >> 3);
    long e0 = g * 4;
    if (e0 >= E) return;
    const uint4* fh = which ? g_p2q : g_xq;
    __half*      ob = which ? (__half*)g_agg2h : (__half*)g_agg1h;
    int4 ss = *(const int4*)(g_src + e0);   // padded arrays: safe at tail
    int4 dd = *(const int4*)(g_dst + e0);
    if (e0 + 4 <= E) {
        float w0, w1, w2, w3;
        if (which == 0) {
            w0 = g_dinv[ss.x] * g_dinv[dd.x];
            w1 = g_dinv[ss.y] * g_dinv[dd.y];
            w2 = g_dinv[ss.z] * g_dinv[dd.z];
            w3 = g_dinv[ss.w] * g_dinv[dd.w];
            if (l == 0) *(float4*)(g_w + e0) = make_float4(w0, w1, w2, w3);
        } else {
            float4 ww = __ldg((const float4*)(g_w + e0));
            w0 = ww.x; w1 = ww.y; w2 = ww.z; w3 = ww.w;
        }
        uint4 r0 = __ldg(fh + (size_t)ss.x * 8 + l);
        uint4 r1 = __ldg(fh + (size_t)ss.y * 8 + l);
        uint4 r2 = __ldg(fh + (size_t)ss.z * 8 + l);
        uint4 r3 = __ldg(fh + (size_t)ss.w * 8 + l);
        r0 = hscale(r0, w0); r1 = hscale(r1, w1);
        r2 = hscale(r2, w2); r3 = hscale(r3, w3);
        red_add_v4h(ob + (size_t)dd.x * 64 + l * 8, r0);
        red_add_v4h(ob + (size_t)dd.y * 64 + l * 8, r1);
        red_add_v4h(ob + (size_t)dd.z * 64 + l * 8, r2);
        red_add_v4h(ob + (size_t)dd.w * 64 + l * 8, r3);
    } else {
        int rem = (int)(E - e0);
        int sa[4] = {ss.x, ss.y, ss.z, ss.w};
        int da[4] = {dd.x, dd.y, dd.z, dd.w};
#pragma unroll 1
        for (int k = 0; k < rem; k++) {
            int s = sa[k], d = da[k];
            float w;
            if (which == 0) {
                w = g_dinv[s] * g_dinv[d];
                if (l == 0) g_w[e0 + k] = w;
            } else {
                w = __ldg(g_w + e0 + k);
            }
            uint4 r = hscale(__ldg(fh + (size_t)s * 8 + l), w);
            red_add_v4h(ob + (size_t)d * 64 + l * 8, r);
        }
    }
}

// Fused GEMM1+GEMM2: p2 = (relu(agg1@W1+b1)) @ W2, h1 never leaves registers.
// GEMM1 C-fragments convert in-register to GEMM2 A-fragments (layout-compatible).
// Writes fp16 p2 mirror + fp16 agg2 self-loop init.
__global__ void __launch_bounds__(256) k_gemm12(const float* __restrict__ W1,
                                                const float* __restrict__ b1,
                                                const float* __restrict__ W2, int N) {
    __shared__ __half W1T[128][72];   // [n][k] padded
    __shared__ __half W2T[64][136];   // [n][k] padded
    __shared__ float bs[128];
    int tid = threadIdx.x;
    for (int i = tid; i < 64 * 128; i += 256) {
        int k = i >> 7, n = i & 127;
        W1T[n][k] = __float2half(W1[i]);
    }
    for (int i = tid; i < 128 * 64; i += 256) {
        int k = i >> 6, n = i & 63;
        W2T[n][k] = __float2half(W2[i]);
    }
    if (tid < 128) bs[tid] = b1[tid];
    __syncthreads();

    int warp = tid >> 5, lane = tid & 31;
    int g = lane >> 2, t = lane & 3;
    long row0 = (long)blockIdx.x * 128 + warp * 16;
    long r0 = row0 + g, r1 = row0 + g + 8;
    long r0c = (r0 < N) ? r0 : (long)(N - 1);
    long r1c = (r1 < N) ? r1 : (long)(N - 1);

    // ---- GEMM1: h1 = relu(agg1 @ W1 + b1), kept in registers ----
    const __half* A0 = (const __half*)g_agg1h + r0c * 64;
    const __half* A1 = (const __half*)g_agg1h + r1c * 64;
    unsigned a1f[4][4];
#pragma unroll
    for (int ks = 0; ks < 4; ks++) {
        int c0i = ks * 16 + t * 2;
        a1f[ks][0] = *(const unsigned*)(A0 + c0i);
        a1f[ks][1] = *(const unsigned*)(A1 + c0i);
        a1f[ks][2] = *(const unsigned*)(A0 + c0i + 8);
        a1f[ks][3] = *(const unsigned*)(A1 + c0i + 8);
    }
    float c0[16], c1[16], c2[16], c3[16];
#pragma unroll
    for (int nb = 0; nb < 16; nb++) {
        int ncol = nb * 8 + t * 2;
        c0[nb] = bs[ncol]; c1[nb] = bs[ncol + 1];
        c2[nb] = c0[nb];   c3[nb] = c1[nb];
#pragma unroll
        for (int ks = 0; ks < 4; ks++) {
            unsigned b0 = *(const unsigned*)&W1T[nb * 8 + g][ks * 16 + t * 2];
            unsigned bq = *(const unsigned*)&W1T[nb * 8 + g][ks * 16 + t * 2 + 8];
            mma16816(c0[nb], c1[nb], c2[nb], c3[nb],
                     a1f[ks][0], a1f[ks][1], a1f[ks][2], a1f[ks][3], b0, bq);
        }
    }
    // ---- in-register relu + repack: C(m16n8 pair) -> A(m16k16) fragments ----
    unsigned a2f[8][4];
#pragma unroll
    for (int ks = 0; ks < 8; ks++) {
        int ne = 2 * ks, no = 2 * ks + 1;
        a2f[ks][0] = h2u2(fmaxf(c0[ne], 0.f), fmaxf(c1[ne], 0.f));
        a2f[ks][1] = h2u2(fmaxf(c2[ne], 0.f), fmaxf(c3[ne], 0.f));
        a2f[ks][2] = h2u2(fmaxf(c0[no], 0.f), fmaxf(c1[no], 0.f));
        a2f[ks][3] = h2u2(fmaxf(c2[no], 0.f), fmaxf(c3[no], 0.f));
    }
    // ---- GEMM2: p2 = h1 @ W2 ----
    float dv0 = g_dinv[r0c], dv1 = g_dinv[r1c];
    float w0 = dv0 * dv0, w1 = dv1 * dv1;
    __half* p2h = (__half*)g_p2q;
    __half* a2h = (__half*)g_agg2h;
#pragma unroll
    for (int nb = 0; nb < 8; nb++) {
        int ncol = nb * 8 + t * 2;
        float d0 = 0.f, d1 = 0.f, d2 = 0.f, d3 = 0.f;
#pragma unroll
        for (int ks = 0; ks < 8; ks++) {
            unsigned b0 = *(const unsigned*)&W2T[nb * 8 + g][ks * 16 + t * 2];
            unsigned bq = *(const unsigned*)&W2T[nb * 8 + g][ks * 16 + t * 2 + 8];
            mma16816(d0, d1, d2, d3,
                     a2f[ks][0], a2f[ks][1], a2f[ks][2], a2f[ks][3], b0, bq);
        }
        if (r0 < N) {
            __half2 h0 = __floats2half2_rn(d0, d1);
            *(unsigned*)&p2h[r0 * 64 + ncol] = *reinterpret_cast<unsigned*>(&h0);
            __half2 s0 = __floats2half2_rn(d0 * w0, d1 * w0);
            *(unsigned*)&a2h[r0 * 64 + ncol] = *reinterpret_cast<unsigned*>(&s0);
        }
        if (r1 < N) {
            __half2 h1 = __floats2half2_rn(d2, d3);
            *(unsigned*)&p2h[r1 * 64 + ncol] = *reinterpret_cast<unsigned*>(&h1);
            __half2 s1 = __floats2half2_rn(d2 * w1, d3 * w1);
            *(unsigned*)&a2h[r1 * 64 + ncol] = *reinterpret_cast<unsigned*>(&s1);
        }
    }
}

// per-node readout: pAB[n] = (dot(relu(agg2+b2), Wc[:64]), dot(relu(agg2+b2), Wc[64:]))
__global__ void __launch_bounds__(256) k_nodescore(const float* __restrict__ Wc,
                                                   const float* __restrict__ b2, int N) {
    int tid = threadIdx.x;
    int l = tid & 15;
    int row = blockIdx.x * 16 + (tid >> 4);
    if (row >= N) return;
    float4 wa = __ldg((const float4*)Wc + l);
    float4 wb = __ldg((const float4*)Wc + 16 + l);
    float4 b4 = __ldg((const float4*)b2 + l);
    float4 v = from_h4(((const uint2*)g_agg2h)[(size_t)row * 16 + l]);
    v.x = fmaxf(v.x + b4.x, 0.f); v.y = fmaxf(v.y + b4.y, 0.f);
    v.z = fmaxf(v.z + b4.z, 0.f); v.w = fmaxf(v.w + b4.w, 0.f);
    float pa = v.x * wa.x + v.y * wa.y + v.z * wa.z + v.w * wa.w;
    float pb = v.x * wb.x + v.y * wb.y + v.z * wb.z + v.w * wb.w;
#pragma unroll
    for (int o = 8; o >= 1; o >>= 1) {
        pa += __shfl_down_sync(0xffffffffu, pa, o, 16);
        pb += __shfl_down_sync(0xffffffffu, pb, o, 16);
    }
    if (l == 0) g_pAB[row] = make_float2(pa, pb);
}

__global__ void __launch_bounds__(256) k_edge(const float* __restrict__ bcp,
                                              float* __restrict__ out, int E) {
    long e = (long)blockIdx.x * 256 + threadIdx.x;
    if (e >= E) return;
    int s = g_src[e], d = g_dst[e];
    float2 ps = __ldg(&g_pAB[s]);
    float2 pd = __ldg(&g_pAB[d]);
    float z = ps.x + pd.y + __ldg(bcp);
    out[e] = 1.0f / (1.0f + __expf(-z));
}

// ---------------- launcher ----------------
extern "C" void kernel_launch(void* const* d_in, const int* in_sizes, int n_in,
                              void* d_out, int out_size) {
    const float* x  = (const float*)d_in[0];
    const void*  ei = d_in[1];
    const float* W1 = (const float*)d_in[2];
    // b1 = d_in[3]
    const float* W2 = (const float*)d_in[4];
    const float* b2 = (const float*)d_in[5];
    const float* Wc = (const float*)d_in[6];
    const float* bc = (const float*)d_in[7];
    const float* b1 = (const float*)d_in[3];
    float* out = (float*)d_out;

    int N = in_sizes[0] / 64;
    int E = in_sizes[1] / 2;
    if (N > N_MAX) N = N_MAX;
    if (E > E_MAX) E = E_MAX;

    int eb128 = (E + 127) / 128;    // 32 groups x 4 edges per block
    int nb16  = (N + 15) / 16;
    int gb    = (N + 127) / 128;
    int ebs   = (E + 255) / 256;

    k_convert  <<<ebs, 256>>>(ei, E);
    k_prep     <<<nb16, 256>>>(x, N);
    k_agg      <<<eb128, 256>>>(E, 0);
    k_gemm12   <<<gb, 256>>>(W1, b1, W2, N);
    k_agg      <<<eb128, 256>>>(E, 1);
    k_nodescore<<<nb16, 256>>>(Wc, b2, N);
    k_edge     <<<ebs, 256>>>(bc, out, E);
}

// round 15
// speedup vs baseline: 3.5346x; 1.0140x over previous
#include <cuda_runtime.h>
#include <cuda_fp16.h>
#include <cuda_bf16.h>

#define N_MAX 100000
#define E_MAX 1000000

// ---------------- device scratch ----------------
__device__ float  g_dinv[N_MAX];
__device__ int    g_cnt[N_MAX];                 // zero at load; k_prep resets after use
__device__ int    g_src[E_MAX + 4];             // +4 pad: int4 loads at tail
__device__ int    g_dst[E_MAX + 4];
__device__ float  g_w  [E_MAX + 4];             // per-edge norm weight (pass-1 caches)
__device__ uint4  g_agg1h[(size_t)N_MAX * 8];   // agg1 fp16: 64 halves/row
__device__ uint4  g_agg2h[(size_t)N_MAX * 8];   // agg2 fp16
__device__ uint4  g_xq  [(size_t)N_MAX * 8];    // x  fp16 rows
__device__ uint4  g_p2q [(size_t)N_MAX * 8];    // p2 fp16 rows
__device__ float2 g_pAB [N_MAX];

// ---------------- helpers ----------------
__device__ __forceinline__ void red_add_v4h(__half* p, uint4 v) {
    asm volatile("red.global.add.noftz.v4.f16x2 [%0], {%1, %2, %3, %4};"
                 :: "l"(p), "r"(v.x), "r"(v.y), "r"(v.z), "r"(v.w)
                 : "memory");
}
__device__ __forceinline__ uint4 hscale(uint4 r, float w) {
    __half2 W = __float2half2_rn(w);
    __half2* h = reinterpret_cast<__half2*>(&r);
    h[0] = __hmul2(h[0], W); h[1] = __hmul2(h[1], W);
    h[2] = __hmul2(h[2], W); h[3] = __hmul2(h[3], W);
    return r;
}
__device__ __forceinline__ uint2 to_h4(float4 v) {
    __half2 a = __floats2half2_rn(v.x, v.y);
    __half2 b = __floats2half2_rn(v.z, v.w);
    uint2 u;
    u.x = *reinterpret_cast<unsigned int*>(&a);
    u.y = *reinterpret_cast<unsigned int*>(&b);
    return u;
}
__device__ __forceinline__ float4 from_h4(uint2 u) {
    __half2 a = *reinterpret_cast<__half2*>(&u.x);
    __half2 b = *reinterpret_cast<__half2*>(&u.y);
    float2 f0 = __half22float2(a);
    float2 f1 = __half22float2(b);
    return make_float4(f0.x, f0.y, f1.x, f1.y);
}
__device__ __forceinline__ unsigned h2u2(float x, float y) {
    __half2 h = __floats2half2_rn(x, y);
    return *reinterpret_cast<unsigned*>(&h);
}
__device__ __forceinline__ void mma16816(float& c0, float& c1, float& c2, float& c3,
                                         unsigned a0, unsigned a1, unsigned a2, unsigned a3,
                                         unsigned b0, unsigned b1) {
    asm volatile(
        "mma.sync.aligned.m16n8k16.row.col.f32.f16.f16.f32 "
        "{%0,%1,%2,%3},{%4,%5,%6,%7},{%8,%9},{%0,%1,%2,%3};"
        : "+f"(c0), "+f"(c1), "+f"(c2), "+f"(c3)
        : "r"(a0), "r"(a1), "r"(a2), "r"(a3), "r"(b0), "r"(b1));
}

// ---------------- kernels ----------------

// Normalize edge_index (int64 OR int32, runtime-detected) + int degree count at dst.
__global__ void __launch_bounds__(256) k_convert(const void* __restrict__ ei, int E) {
    long i = (long)blockIdx.x * 256 + threadIdx.x;
    if (i >= E) return;
    const unsigned long long* p64 = (const unsigned long long*)ei;
    bool is64 = true;
#pragma unroll
    for (int j = 0; j < 8; j++) is64 &= (p64[j] < (unsigned long long)N_MAX);
    int s, d;
    if (is64) {
        s = (int)p64[i];
        d = (int)p64[(long)E + i];
    } else {
        const int* p32 = (const int*)ei;
        s = p32[i];
        d = p32[(long)E + i];
    }
    g_src[i] = s;
    g_dst[i] = d;
    atomicAdd(&g_cnt[d], 1);
}

// dinv = rsqrt(cnt+1) (and reset cnt for next replay); g_xq = fp16(x);
// agg1 init = fp16(x/deg) (self-loop term).
__global__ void __launch_bounds__(256) k_prep(const float* __restrict__ x, int N) {
    int tid = threadIdx.x;
    int l = tid & 15;
    int row = blockIdx.x * 16 + (tid >> 4);
    if (row >= N) return;
    int cnt = g_cnt[row];
    float dv = rsqrtf((float)(cnt + 1));
    if (l == 0) { g_dinv[row] = dv; g_cnt[row] = 0; }
    float w = dv * dv;
    float4 v = __ldg((const float4*)x + (size_t)row * 16 + l);
    ((uint2*)g_xq)[(size_t)row * 16 + l] = to_h4(v);
    v.x *= w; v.y *= w; v.z *= w; v.w *= w;
    ((uint2*)g_agg1h)[(size_t)row * 16 + l] = to_h4(v);
}

// Edge aggregation: 8 lanes per edge, 4 edges per group.
// pass 0: compute w from dinv and CACHE to g_w; pass 1: broadcast-load cached w.
__global__ void __launch_bounds__(256) k_agg(int E, int which) {
    int tid = threadIdx.x;
    int l = tid & 7;
    long g = (long)blockIdx.x * 32 + (tid >> 3);
    long e0 = g * 4;
    if (e0 >= E) return;
    const uint4* fh = which ? g_p2q : g_xq;
    __half*      ob = which ? (__half*)g_agg2h : (__half*)g_agg1h;
    int4 ss = *(const int4*)(g_src + e0);   // padded arrays: safe at tail
    int4 dd = *(const int4*)(g_dst + e0);
    if (e0 + 4 <= E) {
        float w0, w1, w2, w3;
        if (which == 0) {
            w0 = g_dinv[ss.x] * g_dinv[dd.x];
            w1 = g_dinv[ss.y] * g_dinv[dd.y];
            w2 = g_dinv[ss.z] * g_dinv[dd.z];
            w3 = g_dinv[ss.w] * g_dinv[dd.w];
            if (l == 0) *(float4*)(g_w + e0) = make_float4(w0, w1, w2, w3);
        } else {
            float4 ww = __ldg((const float4*)(g_w + e0));
            w0 = ww.x; w1 = ww.y; w2 = ww.z; w3 = ww.w;
        }
        uint4 r0 = __ldg(fh + (size_t)ss.x * 8 + l);
        uint4 r1 = __ldg(fh + (size_t)ss.y * 8 + l);
        uint4 r2 = __ldg(fh + (size_t)ss.z * 8 + l);
        uint4 r3 = __ldg(fh + (size_t)ss.w * 8 + l);
        r0 = hscale(r0, w0); r1 = hscale(r1, w1);
        r2 = hscale(r2, w2); r3 = hscale(r3, w3);
        red_add_v4h(ob + (size_t)dd.x * 64 + l * 8, r0);
        red_add_v4h(ob + (size_t)dd.y * 64 + l * 8, r1);
        red_add_v4h(ob + (size_t)dd.z * 64 + l * 8, r2);
        red_add_v4h(ob + (size_t)dd.w * 64 + l * 8, r3);
    } else {
        int rem = (int)(E - e0);
        int sa[4] = {ss.x, ss.y, ss.z, ss.w};
        int da[4] = {dd.x, dd.y, dd.z, dd.w};
#pragma unroll 1
        for (int k = 0; k < rem; k++) {
            int s = sa[k], d = da[k];
            float w;
            if (which == 0) {
                w = g_dinv[s] * g_dinv[d];
                if (l == 0) g_w[e0 + k] = w;
            } else {
                w = __ldg(g_w + e0 + k);
            }
            uint4 r = hscale(__ldg(fh + (size_t)s * 8 + l), w);
            red_add_v4h(ob + (size_t)d * 64 + l * 8, r);
        }
    }
}

// Fused GEMM1+GEMM2: p2 = (relu(agg1@W1+b1)) @ W2, h1 never leaves registers.
// GEMM1 accumulators are produced PER nb-PAIR and repacked immediately into
// GEMM2 A-fragments (register-layout-compatible) — keeps live regs small so
// >=3 CTAs/SM fit (the round-14 version materialized 64 fp32 accumulators
// and dropped to 2 CTAs/SM, exposing MMA latency).
__global__ void __launch_bounds__(256, 3) k_gemm12(const float* __restrict__ W1,
                                                   const float* __restrict__ b1,
                                                   const float* __restrict__ W2, int N) {
    __shared__ __half W1T[128][72];   // [n][k] padded
    __shared__ __half W2T[64][136];   // [n][k] padded
    __shared__ float bs[128];
    int tid = threadIdx.x;
    for (int i = tid; i < 64 * 128; i += 256) {
        int k = i >> 7, n = i & 127;
        W1T[n][k] = __float2half(W1[i]);
    }
    for (int i = tid; i < 128 * 64; i += 256) {
        int k = i >> 6, n = i & 63;
        W2T[n][k] = __float2half(W2[i]);
    }
    if (tid < 128) bs[tid] = b1[tid];
    __syncthreads();

    int warp = tid >> 5, lane = tid & 31;
    int g = lane >> 2, t = lane & 3;
    long row0 = (long)blockIdx.x * 128 + warp * 16;
    long r0 = row0 + g, r1 = row0 + g + 8;
    long r0c = (r0 < N) ? r0 : (long)(N - 1);
    long r1c = (r1 < N) ? r1 : (long)(N - 1);

    // ---- GEMM1 A-fragments ----
    const __half* A0 = (const __half*)g_agg1h + r0c * 64;
    const __half* A1 = (const __half*)g_agg1h + r1c * 64;
    unsigned a1f[4][4];
#pragma unroll
    for (int ks = 0; ks < 4; ks++) {
        int c0i = ks * 16 + t * 2;
        a1f[ks][0] = *(const unsigned*)(A0 + c0i);
        a1f[ks][1] = *(const unsigned*)(A1 + c0i);
        a1f[ks][2] = *(const unsigned*)(A0 + c0i + 8);
        a1f[ks][3] = *(const unsigned*)(A1 + c0i + 8);
    }

    // ---- GEMM1 interleaved with relu+repack: one nb-pair at a time ----
    unsigned a2f[8][4];
#pragma unroll
    for (int ks = 0; ks < 8; ks++) {
        int ne = 2 * ks, no = ne + 1;
        int nce = ne * 8 + t * 2, nco = no * 8 + t * 2;
        float e0 = bs[nce], e1 = bs[nce + 1], e2 = e0, e3 = e1;
        float o0 = bs[nco], o1 = bs[nco + 1], o2 = o0, o3 = o1;
#pragma unroll
        for (int k1 = 0; k1 < 4; k1++) {
            unsigned be0 = *(const unsigned*)&W1T[ne * 8 + g][k1 * 16 + t * 2];
            unsigned be1 = *(const unsigned*)&W1T[ne * 8 + g][k1 * 16 + t * 2 + 8];
            mma16816(e0, e1, e2, e3,
                     a1f[k1][0], a1f[k1][1], a1f[k1][2], a1f[k1][3], be0, be1);
            unsigned bo0 = *(const unsigned*)&W1T[no * 8 + g][k1 * 16 + t * 2];
            unsigned bo1 = *(const unsigned*)&W1T[no * 8 + g][k1 * 16 + t * 2 + 8];
            mma16816(o0, o1, o2, o3,
                     a1f[k1][0], a1f[k1][1], a1f[k1][2], a1f[k1][3], bo0, bo1);
        }
        a2f[ks][0] = h2u2(fmaxf(e0, 0.f), fmaxf(e1, 0.f));
        a2f[ks][1] = h2u2(fmaxf(e2, 0.f), fmaxf(e3, 0.f));
        a2f[ks][2] = h2u2(fmaxf(o0, 0.f), fmaxf(o1, 0.f));
        a2f[ks][3] = h2u2(fmaxf(o2, 0.f), fmaxf(o3, 0.f));
    }

    // ---- GEMM2: p2 = h1 @ W2 ----
    float dv0 = g_dinv[r0c], dv1 = g_dinv[r1c];
    float w0 = dv0 * dv0, w1 = dv1 * dv1;
    __half* p2h = (__half*)g_p2q;
    __half* a2h = (__half*)g_agg2h;
#pragma unroll
    for (int nb = 0; nb < 8; nb++) {
        int ncol = nb * 8 + t * 2;
        float d0 = 0.f, d1 = 0.f, d2 = 0.f, d3 = 0.f;
#pragma unroll
        for (int ks = 0; ks < 8; ks++) {
            unsigned b0 = *(const unsigned*)&W2T[nb * 8 + g][ks * 16 + t * 2];
            unsigned bq = *(const unsigned*)&W2T[nb * 8 + g][ks * 16 + t * 2 + 8];
            mma16816(d0, d1, d2, d3,
                     a2f[ks][0], a2f[ks][1], a2f[ks][2], a2f[ks][3], b0, bq);
        }
        if (r0 < N) {
            __half2 h0 = __floats2half2_rn(d0, d1);
            *(unsigned*)&p2h[r0 * 64 + ncol] = *reinterpret_cast<unsigned*>(&h0);
            __half2 s0 = __floats2half2_rn(d0 * w0, d1 * w0);
            *(unsigned*)&a2h[r0 * 64 + ncol] = *reinterpret_cast<unsigned*>(&s0);
        }
        if (r1 < N) {
            __half2 h1 = __floats2half2_rn(d2, d3);
            *(unsigned*)&p2h[r1 * 64 + ncol] = *reinterpret_cast<unsigned*>(&h1);
            __half2 s1 = __floats2half2_rn(d2 * w1, d3 * w1);
            *(unsigned*)&a2h[r1 * 64 + ncol] = *reinterpret_cast<unsigned*>(&s1);
        }
    }
}

// per-node readout: pAB[n] = (dot(relu(agg2+b2), Wc[:64]), dot(relu(agg2+b2), Wc[64:]))
__global__ void __launch_bounds__(256) k_nodescore(const float* __restrict__ Wc,
                                                   const float* __restrict__ b2, int N) {
    int tid = threadIdx.x;
    int l = tid & 15;
    int row = blockIdx.x * 16 + (tid >> 4);
    if (row >= N) return;
    float4 wa = __ldg((const float4*)Wc + l);
    float4 wb = __ldg((const float4*)Wc + 16 + l);
    float4 b4 = __ldg((const float4*)b2 + l);
    float4 v = from_h4(((const uint2*)g_agg2h)[(size_t)row * 16 + l]);
    v.x = fmaxf(v.x + b4.x, 0.f); v.y = fmaxf(v.y + b4.y, 0.f);
    v.z = fmaxf(v.z + b4.z, 0.f); v.w = fmaxf(v.w + b4.w, 0.f);
    float pa = v.x * wa.x + v.y * wa.y + v.z * wa.z + v.w * wa.w;
    float pb = v.x * wb.x + v.y * wb.y + v.z * wb.z + v.w * wb.w;
#pragma unroll
    for (int o = 8; o >= 1; o >>= 1) {
        pa += __shfl_down_sync(0xffffffffu, pa, o, 16);
        pb += __shfl_down_sync(0xffffffffu, pb, o, 16);
    }
    if (l == 0) g_pAB[row] = make_float2(pa, pb);
}

__global__ void __launch_bounds__(256) k_edge(const float* __restrict__ bcp,
                                              float* __restrict__ out, int E) {
    long e = (long)blockIdx.x * 256 + threadIdx.x;
    if (e >= E) return;
    int s = g_src[e], d = g_dst[e];
    float2 ps = __ldg(&g_pAB[s]);
    float2 pd = __ldg(&g_pAB[d]);
    float z = ps.x + pd.y + __ldg(bcp);
    out[e] = 1.0f / (1.0f + __expf(-z));
}

// ---------------- launcher ----------------
extern "C" void kernel_launch(void* const* d_in, const int* in_sizes, int n_in,
                              void* d_out, int out_size) {
    const float* x  = (const float*)d_in[0];
    const void*  ei = d_in[1];
    const float* W1 = (const float*)d_in[2];
    const float* b1 = (const float*)d_in[3];
    const float* W2 = (const float*)d_in[4];
    const float* b2 = (const float*)d_in[5];
    const float* Wc = (const float*)d_in[6];
    const float* bc = (const float*)d_in[7];
    float* out = (float*)d_out;

    int N = in_sizes[0] / 64;
    int E = in_sizes[1] / 2;
    if (N > N_MAX) N = N_MAX;
    if (E > E_MAX) E = E_MAX;

    int eb128 = (E + 127) / 128;    // 32 groups x 4 edges per block
    int nb16  = (N + 15) / 16;
    int gb    = (N + 127) / 128;
    int ebs   = (E + 255) / 256;

    k_convert  <<<ebs, 256>>>(ei, E);
    k_prep     <<<nb16, 256>>>(x, N);
    k_agg      <<<eb128, 256>>>(E, 0);
    k_gemm12   <<<gb, 256>>>(W1, b1, W2, N);
    k_agg      <<<eb128, 256>>>(E, 1);
    k_nodescore<<<nb16, 256>>>(Wc, b2, N);
    k_edge     <<<ebs, 256>>>(bc, out, E);
}

// round 16
// speedup vs baseline: 3.6472x; 1.0319x over previous
#include <cuda_runtime.h>
#include <cuda_fp16.h>
#include <cuda_bf16.h>

#define N_MAX 100000
#define E_MAX 1000000

// ---------------- device scratch ----------------
__device__ float  g_dinv[N_MAX];
__device__ int    g_cnt[N_MAX];                 // zero at load; k_prep resets after use
__device__ int    g_src[E_MAX + 4];             // +4 pad: int4 loads at tail
__device__ int    g_dst[E_MAX + 4];
__device__ float  g_w  [E_MAX + 4];             // per-edge norm weight (pass-1 caches)
__device__ uint4  g_agg1h[(size_t)N_MAX * 8];   // agg1 fp16: 64 halves/row
__device__ uint4  g_agg2h[(size_t)N_MAX * 8];   // agg2 fp16
__device__ uint4  g_xq  [(size_t)N_MAX * 8];    // x  fp16 rows
__device__ uint4  g_p2q [(size_t)N_MAX * 8];    // p2 fp16 rows
__device__ float2 g_pAB [N_MAX];

// ---------------- helpers ----------------
__device__ __forceinline__ void red_add_v4h(__half* p, uint4 v) {
    asm volatile("red.global.add.noftz.v4.f16x2 [%0], {%1, %2, %3, %4};"
                 :: "l"(p), "r"(v.x), "r"(v.y), "r"(v.z), "r"(v.w)
                 : "memory");
}
__device__ __forceinline__ uint4 hscale(uint4 r, float w) {
    __half2 W = __float2half2_rn(w);
    __half2* h = reinterpret_cast<__half2*>(&r);
    h[0] = __hmul2(h[0], W); h[1] = __hmul2(h[1], W);
    h[2] = __hmul2(h[2], W); h[3] = __hmul2(h[3], W);
    return r;
}
__device__ __forceinline__ uint2 to_h4(float4 v) {
    __half2 a = __floats2half2_rn(v.x, v.y);
    __half2 b = __floats2half2_rn(v.z, v.w);
    uint2 u;
    u.x = *reinterpret_cast<unsigned int*>(&a);
    u.y = *reinterpret_cast<unsigned int*>(&b);
    return u;
}
__device__ __forceinline__ float4 from_h4(uint2 u) {
    __half2 a = *reinterpret_cast<__half2*>(&u.x);
    __half2 b = *reinterpret_cast<__half2*>(&u.y);
    float2 f0 = __half22float2(a);
    float2 f1 = __half22float2(b);
    return make_float4(f0.x, f0.y, f1.x, f1.y);
}
__device__ __forceinline__ unsigned h2u2(float x, float y) {
    __half2 h = __floats2half2_rn(x, y);
    return *reinterpret_cast<unsigned*>(&h);
}
__device__ __forceinline__ void mma16816(float& c0, float& c1, float& c2, float& c3,
                                         unsigned a0, unsigned a1, unsigned a2, unsigned a3,
                                         unsigned b0, unsigned b1) {
    asm volatile(
        "mma.sync.aligned.m16n8k16.row.col.f32.f16.f16.f32 "
        "{%0,%1,%2,%3},{%4,%5,%6,%7},{%8,%9},{%0,%1,%2,%3};"
        : "+f"(c0), "+f"(c1), "+f"(c2), "+f"(c3)
        : "r"(a0), "r"(a1), "r"(a2), "r"(a3), "r"(b0), "r"(b1));
}

// ---------------- kernels ----------------

// Normalize edge_index (int64 OR int32, runtime-detected) + int degree count at dst.
__global__ void __launch_bounds__(256) k_convert(const void* __restrict__ ei, int E) {
    long i = (long)blockIdx.x * 256 + threadIdx.x;
    if (i >= E) return;
    const unsigned long long* p64 = (const unsigned long long*)ei;
    bool is64 = true;
#pragma unroll
    for (int j = 0; j < 8; j++) is64 &= (p64[j] < (unsigned long long)N_MAX);
    int s, d;
    if (is64) {
        s = (int)p64[i];
        d = (int)p64[(long)E + i];
    } else {
        const int* p32 = (const int*)ei;
        s = p32[i];
        d = p32[(long)E + i];
    }
    g_src[i] = s;
    g_dst[i] = d;
    atomicAdd(&g_cnt[d], 1);
}

// dinv = rsqrt(cnt+1) (and reset cnt for next replay); g_xq = fp16(x);
// agg1 init = fp16(x/deg) (self-loop term).
__global__ void __launch_bounds__(256) k_prep(const float* __restrict__ x, int N) {
    int tid = threadIdx.x;
    int l = tid & 15;
    int row = blockIdx.x * 16 + (tid >> 4);
    if (row >= N) return;
    int cnt = g_cnt[row];
    float dv = rsqrtf((float)(cnt + 1));
    if (l == 0) { g_dinv[row] = dv; g_cnt[row] = 0; }
    float w = dv * dv;
    float4 v = __ldg((const float4*)x + (size_t)row * 16 + l);
    ((uint2*)g_xq)[(size_t)row * 16 + l] = to_h4(v);
    v.x *= w; v.y *= w; v.z *= w; v.w *= w;
    ((uint2*)g_agg1h)[(size_t)row * 16 + l] = to_h4(v);
}

// Edge aggregation: 8 lanes per edge, 4 edges per group.
// pass 0: compute w from dinv and CACHE to g_w; pass 1: broadcast-load cached w.
__global__ void __launch_bounds__(256) k_agg(int E, int which) {
    int tid = threadIdx.x;
    int l = tid & 7;
    long g = (long)blockIdx.x * 32 + (tid >> 3);
    long e0 = g * 4;
    if (e0 >= E) return;
    const uint4* fh = which ? g_p2q : g_xq;
    __half*      ob = which ? (__half*)g_agg2h : (__half*)g_agg1h;
    int4 ss = *(const int4*)(g_src + e0);   // padded arrays: safe at tail
    int4 dd = *(const int4*)(g_dst + e0);
    if (e0 + 4 <= E) {
        float w0, w1, w2, w3;
        if (which == 0) {
            w0 = g_dinv[ss.x] * g_dinv[dd.x];
            w1 = g_dinv[ss.y] * g_dinv[dd.y];
            w2 = g_dinv[ss.z] * g_dinv[dd.z];
            w3 = g_dinv[ss.w] * g_dinv[dd.w];
            if (l == 0) *(float4*)(g_w + e0) = make_float4(w0, w1, w2, w3);
        } else {
            float4 ww = __ldg((const float4*)(g_w + e0));
            w0 = ww.x; w1 = ww.y; w2 = ww.z; w3 = ww.w;
        }
        uint4 r0 = __ldg(fh + (size_t)ss.x * 8 + l);
        uint4 r1 = __ldg(fh + (size_t)ss.y * 8 + l);
        uint4 r2 = __ldg(fh + (size_t)ss.z * 8 + l);
        uint4 r3 = __ldg(fh + (size_t)ss.w * 8 + l);
        r0 = hscale(r0, w0); r1 = hscale(r1, w1);
        r2 = hscale(r2, w2); r3 = hscale(r3, w3);
        red_add_v4h(ob + (size_t)dd.x * 64 + l * 8, r0);
        red_add_v4h(ob + (size_t)dd.y * 64 + l * 8, r1);
        red_add_v4h(ob + (size_t)dd.z * 64 + l * 8, r2);
        red_add_v4h(ob + (size_t)dd.w * 64 + l * 8, r3);
    } else {
        int rem = (int)(E - e0);
        int sa[4] = {ss.x, ss.y, ss.z, ss.w};
        int da[4] = {dd.x, dd.y, dd.z, dd.w};
#pragma unroll 1
        for (int k = 0; k < rem; k++) {
            int s = sa[k], d = da[k];
            float w;
            if (which == 0) {
                w = g_dinv[s] * g_dinv[d];
                if (l == 0) g_w[e0 + k] = w;
            } else {
                w = __ldg(g_w + e0 + k);
            }
            uint4 r = hscale(__ldg(fh + (size_t)s * 8 + l), w);
            red_add_v4h(ob + (size_t)d * 64 + l * 8, r);
        }
    }
}

// Fused GEMM1+GEMM2: p2 = (relu(agg1@W1+b1)) @ W2, h1 never leaves registers.
// W staged as FRAGMENT-ORDERED smem: GEMM1 reads one LDS.128 per (nb-pair,k)
// (was 4x LDS.32), GEMM2 one LDS.64 per MMA (was 2x LDS.32) -> per-thread LDS
// count 384 -> 96. GEMM2 runs TWO independent accumulation chains (nb pairs)
// to hide HMMA latency (round-15 had a single 8-deep serial chain).
__global__ void __launch_bounds__(256, 3) k_gemm12(const float* __restrict__ W1,
                                                   const float* __restrict__ b1,
                                                   const float* __restrict__ W2, int N) {
    // F1[(p*4+k1)*32 + lane] : uint4 {be0,be1,bo0,bo1} for GEMM1 nb-pair p, k-step k1
    // F2[(nb*8+ks)*32 + lane]: uint2 {b0,b1}          for GEMM2 col-block nb, k-step ks
    __shared__ uint4 F1[8 * 4 * 32];    // 16 KB
    __shared__ uint2 F2[8 * 8 * 32];    // 16 KB
    __shared__ float bs[128];
    int tid = threadIdx.x;
    for (int i = tid; i < 1024; i += 256) {
        int lane = i & 31;
        int k1 = (i >> 5) & 3;
        int p  = i >> 7;
        int gg = lane >> 2, tt = lane & 3;
        int n = p * 16 + gg;            // ne*8+g ; n+8 = no*8+g
        int k = k1 * 16 + tt * 2;
        F1[i] = make_uint4(
            h2u2(W1[k * 128 + n],        W1[(k + 1) * 128 + n]),
            h2u2(W1[(k + 8) * 128 + n],  W1[(k + 9) * 128 + n]),
            h2u2(W1[k * 128 + n + 8],    W1[(k + 1) * 128 + n + 8]),
            h2u2(W1[(k + 8) * 128 + n + 8], W1[(k + 9) * 128 + n + 8]));
    }
    for (int i = tid; i < 2048; i += 256) {
        int lane = i & 31;
        int ks = (i >> 5) & 7;
        int nb = i >> 8;
        int gg = lane >> 2, tt = lane & 3;
        int n = nb * 8 + gg;
        int k = ks * 16 + tt * 2;
        F2[i] = make_uint2(h2u2(W2[k * 64 + n],       W2[(k + 1) * 64 + n]),
                           h2u2(W2[(k + 8) * 64 + n], W2[(k + 9) * 64 + n]));
    }
    if (tid < 128) bs[tid] = b1[tid];
    __syncthreads();

    int warp = tid >> 5, lane = tid & 31;
    int g = lane >> 2, t = lane & 3;
    long row0 = (long)blockIdx.x * 128 + warp * 16;
    long r0 = row0 + g, r1 = row0 + g + 8;
    long r0c = (r0 < N) ? r0 : (long)(N - 1);
    long r1c = (r1 < N) ? r1 : (long)(N - 1);

    // ---- GEMM1 A-fragments ----
    const __half* A0 = (const __half*)g_agg1h + r0c * 64;
    const __half* A1 = (const __half*)g_agg1h + r1c * 64;
    unsigned a1f[4][4];
#pragma unroll
    for (int ks = 0; ks < 4; ks++) {
        int c0i = ks * 16 + t * 2;
        a1f[ks][0] = *(const unsigned*)(A0 + c0i);
        a1f[ks][1] = *(const unsigned*)(A1 + c0i);
        a1f[ks][2] = *(const unsigned*)(A0 + c0i + 8);
        a1f[ks][3] = *(const unsigned*)(A1 + c0i + 8);
    }

    // ---- GEMM1: one nb-pair (2 chains) at a time; relu+repack immediately ----
    unsigned a2f[8][4];
#pragma unroll
    for (int p = 0; p < 8; p++) {
        int nce = (2 * p) * 8 + t * 2, nco = (2 * p + 1) * 8 + t * 2;
        float e0 = bs[nce], e1 = bs[nce + 1], e2 = e0, e3 = e1;
        float o0 = bs[nco], o1 = bs[nco + 1], o2 = o0, o3 = o1;
#pragma unroll
        for (int k1 = 0; k1 < 4; k1++) {
            uint4 f = F1[(p * 4 + k1) * 32 + lane];
            mma16816(e0, e1, e2, e3,
                     a1f[k1][0], a1f[k1][1], a1f[k1][2], a1f[k1][3], f.x, f.y);
            mma16816(o0, o1, o2, o3,
                     a1f[k1][0], a1f[k1][1], a1f[k1][2], a1f[k1][3], f.z, f.w);
        }
        a2f[p][0] = h2u2(fmaxf(e0, 0.f), fmaxf(e1, 0.f));
        a2f[p][1] = h2u2(fmaxf(e2, 0.f), fmaxf(e3, 0.f));
        a2f[p][2] = h2u2(fmaxf(o0, 0.f), fmaxf(o1, 0.f));
        a2f[p][3] = h2u2(fmaxf(o2, 0.f), fmaxf(o3, 0.f));
    }

    // ---- GEMM2: p2 = h1 @ W2, two independent nb chains per step ----
    float dv0 = g_dinv[r0c], dv1 = g_dinv[r1c];
    float w0 = dv0 * dv0, w1 = dv1 * dv1;
    __half* p2h = (__half*)g_p2q;
    __half* a2h = (__half*)g_agg2h;
#pragma unroll
    for (int nb = 0; nb < 8; nb += 2) {
        float d0 = 0.f, d1 = 0.f, d2 = 0.f, d3 = 0.f;
        float q0 = 0.f, q1 = 0.f, q2 = 0.f, q3 = 0.f;
#pragma unroll
        for (int ks = 0; ks < 8; ks++) {
            uint2 fa = F2[(nb * 8 + ks) * 32 + lane];
            uint2 fb = F2[((nb + 1) * 8 + ks) * 32 + lane];
            mma16816(d0, d1, d2, d3,
                     a2f[ks][0], a2f[ks][1], a2f[ks][2], a2f[ks][3], fa.x, fa.y);
            mma16816(q0, q1, q2, q3,
                     a2f[ks][0], a2f[ks][1], a2f[ks][2], a2f[ks][3], fb.x, fb.y);
        }
        int nc0 = nb * 8 + t * 2, nc1 = (nb + 1) * 8 + t * 2;
        if (r0 < N) {
            __half2 h0 = __floats2half2_rn(d0, d1);
            __half2 hq = __floats2half2_rn(q0, q1);
            *(unsigned*)&p2h[r0 * 64 + nc0] = *reinterpret_cast<unsigned*>(&h0);
            *(unsigned*)&p2h[r0 * 64 + nc1] = *reinterpret_cast<unsigned*>(&hq);
            __half2 s0 = __floats2half2_rn(d0 * w0, d1 * w0);
            __half2 sq = __floats2half2_rn(q0 * w0, q1 * w0);
            *(unsigned*)&a2h[r0 * 64 + nc0] = *reinterpret_cast<unsigned*>(&s0);
            *(unsigned*)&a2h[r0 * 64 + nc1] = *reinterpret_cast<unsigned*>(&sq);
        }
        if (r1 < N) {
            __half2 h1 = __floats2half2_rn(d2, d3);
            __half2 hr = __floats2half2_rn(q2, q3);
            *(unsigned*)&p2h[r1 * 64 + nc0] = *reinterpret_cast<unsigned*>(&h1);
            *(unsigned*)&p2h[r1 * 64 + nc1] = *reinterpret_cast<unsigned*>(&hr);
            __half2 s1 = __floats2half2_rn(d2 * w1, d3 * w1);
            __half2 sr = __floats2half2_rn(q2 * w1, q3 * w1);
            *(unsigned*)&a2h[r1 * 64 + nc0] = *reinterpret_cast<unsigned*>(&s1);
            *(unsigned*)&a2h[r1 * 64 + nc1] = *reinterpret_cast<unsigned*>(&sr);
        }
    }
}

// per-node readout: pAB[n] = (dot(relu(agg2+b2), Wc[:64]), dot(relu(agg2+b2), Wc[64:]))
__global__ void __launch_bounds__(256) k_nodescore(const float* __restrict__ Wc,
                                                   const float* __restrict__ b2, int N) {
    int tid = threadIdx.x;
    int l = tid & 15;
    int row = blockIdx.x * 16 + (tid >> 4);
    if (row >= N) return;
    float4 wa = __ldg((const float4*)Wc + l);
    float4 wb = __ldg((const float4*)Wc + 16 + l);
    float4 b4 = __ldg((const float4*)b2 + l);
    float4 v = from_h4(((const uint2*)g_agg2h)[(size_t)row * 16 + l]);
    v.x = fmaxf(v.x + b4.x, 0.f); v.y = fmaxf(v.y + b4.y, 0.f);
    v.z = fmaxf(v.z + b4.z, 0.f); v.w = fmaxf(v.w + b4.w, 0.f);
    float pa = v.x * wa.x + v.y * wa.y + v.z * wa.z + v.w * wa.w;
    float pb = v.x * wb.x + v.y * wb.y + v.z * wb.z + v.w * wb.w;
#pragma unroll
    for (int o = 8; o >= 1; o >>= 1) {
        pa += __shfl_down_sync(0xffffffffu, pa, o, 16);
        pb += __shfl_down_sync(0xffffffffu, pb, o, 16);
    }
    if (l == 0) g_pAB[row] = make_float2(pa, pb);
}

__global__ void __launch_bounds__(256) k_edge(const float* __restrict__ bcp,
                                              float* __restrict__ out, int E) {
    long e = (long)blockIdx.x * 256 + threadIdx.x;
    if (e >= E) return;
    int s = g_src[e], d = g_dst[e];
    float2 ps = __ldg(&g_pAB[s]);
    float2 pd = __ldg(&g_pAB[d]);
    float z = ps.x + pd.y + __ldg(bcp);
    out[e] = 1.0f / (1.0f + __expf(-z));
}

// ---------------- launcher ----------------
extern "C" void kernel_launch(void* const* d_in, const int* in_sizes, int n_in,
                              void* d_out, int out_size) {
    const float* x  = (const float*)d_in[0];
    const void*  ei = d_in[1];
    const float* W1 = (const float*)d_in[2];
    const float* b1 = (const float*)d_in[3];
    const float* W2 = (const float*)d_in[4];
    const float* b2 = (const float*)d_in[5];
    const float* Wc = (const float*)d_in[6];
    const float* bc = (const float*)d_in[7];
    float* out = (float*)d_out;

    int N = in_sizes[0] / 64;
    int E = in_sizes[1] / 2;
    if (N > N_MAX) N = N_MAX;
    if (E > E_MAX) E = E_MAX;

    int eb128 = (E + 127) / 128;    // 32 groups x 4 edges per block
    int nb16  = (N + 15) / 16;
    int gb    = (N + 127) / 128;
    int ebs   = (E + 255) / 256;

    k_convert  <<<ebs, 256>>>(ei, E);
    k_prep     <<<nb16, 256>>>(x, N);
    k_agg      <<<eb128, 256>>>(E, 0);
    k_gemm12   <<<gb, 256>>>(W1, b1, W2, N);
    k_agg      <<<eb128, 256>>>(E, 1);
    k_nodescore<<<nb16, 256>>>(Wc, b2, N);
    k_edge     <<<ebs, 256>>>(bc, out, E);
}

// round 17
// speedup vs baseline: 3.8579x; 1.0578x over previous
#include <cuda_runtime.h>
#include <cuda_fp16.h>
#include <cuda_bf16.h>

#define N_MAX 100000
#define E_MAX 1000000

// ---------------- device scratch ----------------
__device__ float  g_dinv[N_MAX];
__device__ int    g_cnt[N_MAX];                 // zero at load; k_prep resets after use
__device__ int    g_src[E_MAX + 4];             // +4 pad: int4 loads at tail
__device__ int    g_dst[E_MAX + 4];
__device__ float  g_w  [E_MAX + 4];             // per-edge norm weight (pass-1 caches)
__device__ uint4  g_agg1h[(size_t)N_MAX * 8];   // agg1 fp16: 64 halves/row
__device__ uint4  g_agg2h[(size_t)N_MAX * 8];   // agg2 fp16
__device__ uint4  g_xq  [(size_t)N_MAX * 8];    // x  fp16 rows
__device__ uint4  g_p2q [(size_t)N_MAX * 8];    // p2 fp16 rows
__device__ float2 g_pAB [N_MAX];
__device__ uint4  g_F1 [1024];                  // W1 fragment-ordered fp16
__device__ uint4  g_F2 [1024];                  // W2 fragment-ordered fp16 (nb-paired)

// ---------------- helpers ----------------
__device__ __forceinline__ void red_add_v4h(__half* p, uint4 v) {
    asm volatile("red.global.add.noftz.v4.f16x2 [%0], {%1, %2, %3, %4};"
                 :: "l"(p), "r"(v.x), "r"(v.y), "r"(v.z), "r"(v.w)
                 : "memory");
}
__device__ __forceinline__ uint4 hscale(uint4 r, float w) {
    __half2 W = __float2half2_rn(w);
    __half2* h = reinterpret_cast<__half2*>(&r);
    h[0] = __hmul2(h[0], W); h[1] = __hmul2(h[1], W);
    h[2] = __hmul2(h[2], W); h[3] = __hmul2(h[3], W);
    return r;
}
__device__ __forceinline__ uint2 to_h4(float4 v) {
    __half2 a = __floats2half2_rn(v.x, v.y);
    __half2 b = __floats2half2_rn(v.z, v.w);
    uint2 u;
    u.x = *reinterpret_cast<unsigned int*>(&a);
    u.y = *reinterpret_cast<unsigned int*>(&b);
    return u;
}
__device__ __forceinline__ float4 from_h4(uint2 u) {
    __half2 a = *reinterpret_cast<__half2*>(&u.x);
    __half2 b = *reinterpret_cast<__half2*>(&u.y);
    float2 f0 = __half22float2(a);
    float2 f1 = __half22float2(b);
    return make_float4(f0.x, f0.y, f1.x, f1.y);
}
__device__ __forceinline__ unsigned h2u2(float x, float y) {
    __half2 h = __floats2half2_rn(x, y);
    return *reinterpret_cast<unsigned*>(&h);
}
__device__ __forceinline__ void mma16816(float& c0, float& c1, float& c2, float& c3,
                                         unsigned a0, unsigned a1, unsigned a2, unsigned a3,
                                         unsigned b0, unsigned b1) {
    asm volatile(
        "mma.sync.aligned.m16n8k16.row.col.f32.f16.f16.f32 "
        "{%0,%1,%2,%3},{%4,%5,%6,%7},{%8,%9},{%0,%1,%2,%3};"
        : "+f"(c0), "+f"(c1), "+f"(c2), "+f"(c3)
        : "r"(a0), "r"(a1), "r"(a2), "r"(a3), "r"(b0), "r"(b1));
}

// ---------------- kernels ----------------

// Normalize edge_index (int64 OR int32, runtime-detected) + int degree count at dst.
__global__ void __launch_bounds__(256) k_convert(const void* __restrict__ ei, int E) {
    long i = (long)blockIdx.x * 256 + threadIdx.x;
    if (i >= E) return;
    const unsigned long long* p64 = (const unsigned long long*)ei;
    bool is64 = true;
#pragma unroll
    for (int j = 0; j < 8; j++) is64 &= (p64[j] < (unsigned long long)N_MAX);
    int s, d;
    if (is64) {
        s = (int)p64[i];
        d = (int)p64[(long)E + i];
    } else {
        const int* p32 = (const int*)ei;
        s = p32[i];
        d = p32[(long)E + i];
    }
    g_src[i] = s;
    g_dst[i] = d;
    atomicAdd(&g_cnt[d], 1);
}

// One-time: W1/W2 -> fragment-ordered fp16 global arrays.
// g_F1[(p*4+k1)*32+lane] = {be0,be1,bo0,bo1} for GEMM1 nb-pair p (nb=2p,2p+1)
// g_F2[(p*8+ks)*32+lane] = {ba0,ba1,bb0,bb1} for GEMM2 nb-pair p
__global__ void __launch_bounds__(256) k_wprep(const float* __restrict__ W1,
                                               const float* __restrict__ W2) {
    int i = blockIdx.x * 256 + threadIdx.x;
    if (i < 1024) {
        int lane = i & 31;
        int k1 = (i >> 5) & 3;
        int p  = i >> 7;
        int gg = lane >> 2, tt = lane & 3;
        int n = p * 16 + gg;
        int k = k1 * 16 + tt * 2;
        g_F1[i] = make_uint4(
            h2u2(W1[k * 128 + n],           W1[(k + 1) * 128 + n]),
            h2u2(W1[(k + 8) * 128 + n],     W1[(k + 9) * 128 + n]),
            h2u2(W1[k * 128 + n + 8],       W1[(k + 1) * 128 + n + 8]),
            h2u2(W1[(k + 8) * 128 + n + 8], W1[(k + 9) * 128 + n + 8]));
    } else if (i < 2048) {
        int j = i - 1024;
        int lane = j & 31;
        int ks = (j >> 5) & 7;
        int p  = j >> 8;
        int gg = lane >> 2, tt = lane & 3;
        int n0 = (2 * p) * 8 + gg, n1 = (2 * p + 1) * 8 + gg;
        int k = ks * 16 + tt * 2;
        g_F2[j] = make_uint4(
            h2u2(W2[k * 64 + n0],       W2[(k + 1) * 64 + n0]),
            h2u2(W2[(k + 8) * 64 + n0], W2[(k + 9) * 64 + n0]),
            h2u2(W2[k * 64 + n1],       W2[(k + 1) * 64 + n1]),
            h2u2(W2[(k + 8) * 64 + n1], W2[(k + 9) * 64 + n1]));
    }
}

// dinv = rsqrt(cnt+1) (and reset cnt for next replay); g_xq = fp16(x);
// agg1 init = fp16(x/deg) (self-loop term).
__global__ void __launch_bounds__(256) k_prep(const float* __restrict__ x, int N) {
    int tid = threadIdx.x;
    int l = tid & 15;
    int row = blockIdx.x * 16 + (tid >> 4);
    if (row >= N) return;
    int cnt = g_cnt[row];
    float dv = rsqrtf((float)(cnt + 1));
    if (l == 0) { g_dinv[row] = dv; g_cnt[row] = 0; }
    float w = dv * dv;
    float4 v = __ldg((const float4*)x + (size_t)row * 16 + l);
    ((uint2*)g_xq)[(size_t)row * 16 + l] = to_h4(v);
    v.x *= w; v.y *= w; v.z *= w; v.w *= w;
    ((uint2*)g_agg1h)[(size_t)row * 16 + l] = to_h4(v);
}

// Edge aggregation: 8 lanes per edge, 4 edges per group.
// pass 0: compute w from dinv and CACHE to g_w; pass 1: broadcast-load cached w.
__global__ void __launch_bounds__(256) k_agg(int E, int which) {
    int tid = threadIdx.x;
    int l = tid & 7;
    long g = (long)blockIdx.x * 32 + (tid >> 3);
    long e0 = g * 4;
    if (e0 >= E) return;
    const uint4* fh = which ? g_p2q : g_xq;
    __half*      ob = which ? (__half*)g_agg2h : (__half*)g_agg1h;
    int4 ss = *(const int4*)(g_src + e0);   // padded arrays: safe at tail
    int4 dd = *(const int4*)(g_dst + e0);
    if (e0 + 4 <= E) {
        float w0, w1, w2, w3;
        if (which == 0) {
            w0 = g_dinv[ss.x] * g_dinv[dd.x];
            w1 = g_dinv[ss.y] * g_dinv[dd.y];
            w2 = g_dinv[ss.z] * g_dinv[dd.z];
            w3 = g_dinv[ss.w] * g_dinv[dd.w];
            if (l == 0) *(float4*)(g_w + e0) = make_float4(w0, w1, w2, w3);
        } else {
            float4 ww = __ldg((const float4*)(g_w + e0));
            w0 = ww.x; w1 = ww.y; w2 = ww.z; w3 = ww.w;
        }
        uint4 r0 = __ldg(fh + (size_t)ss.x * 8 + l);
        uint4 r1 = __ldg(fh + (size_t)ss.y * 8 + l);
        uint4 r2 = __ldg(fh + (size_t)ss.z * 8 + l);
        uint4 r3 = __ldg(fh + (size_t)ss.w * 8 + l);
        r0 = hscale(r0, w0); r1 = hscale(r1, w1);
        r2 = hscale(r2, w2); r3 = hscale(r3, w3);
        red_add_v4h(ob + (size_t)dd.x * 64 + l * 8, r0);
        red_add_v4h(ob + (size_t)dd.y * 64 + l * 8, r1);
        red_add_v4h(ob + (size_t)dd.z * 64 + l * 8, r2);
        red_add_v4h(ob + (size_t)dd.w * 64 + l * 8, r3);
    } else {
        int rem = (int)(E - e0);
        int sa[4] = {ss.x, ss.y, ss.z, ss.w};
        int da[4] = {dd.x, dd.y, dd.z, dd.w};
#pragma unroll 1
        for (int k = 0; k < rem; k++) {
            int s = sa[k], d = da[k];
            float w;
            if (which == 0) {
                w = g_dinv[s] * g_dinv[d];
                if (l == 0) g_w[e0 + k] = w;
            } else {
                w = __ldg(g_w + e0 + k);
            }
            uint4 r = hscale(__ldg(fh + (size_t)s * 8 + l), w);
            red_add_v4h(ob + (size_t)d * 64 + l * 8, r);
        }
    }
}

// Fused GEMM1+GEMM2 with pre-converted fragment weights.
// Each warp processes TWO 16-row tiles (256 rows/block): W-fill and LDS are
// amortized 2x and every MMA phase runs 4 independent accumulation chains.
__global__ void __launch_bounds__(256, 2) k_gemm12(const float* __restrict__ b1, int N) {
    __shared__ uint4 F1s[1024];     // 16 KB
    __shared__ uint4 F2s[1024];     // 16 KB
    __shared__ float bs[128];
    int tid = threadIdx.x;
    for (int i = tid; i < 1024; i += 256) {
        F1s[i] = g_F1[i];
        F2s[i] = g_F2[i];
    }
    if (tid < 128) bs[tid] = b1[tid];
    __syncthreads();

    int warp = tid >> 5, lane = tid & 31;
    int g = lane >> 2, t = lane & 3;
    long base = (long)blockIdx.x * 256 + warp * 32;

    long r0[2], r1[2], r0c[2], r1c[2];
#pragma unroll
    for (int tl = 0; tl < 2; tl++) {
        r0[tl] = base + tl * 16 + g;
        r1[tl] = r0[tl] + 8;
        r0c[tl] = (r0[tl] < N) ? r0[tl] : (long)(N - 1);
        r1c[tl] = (r1[tl] < N) ? r1[tl] : (long)(N - 1);
    }

    // ---- GEMM1 A-fragments (both tiles) ----
    unsigned a1f[2][4][4];
#pragma unroll
    for (int tl = 0; tl < 2; tl++) {
        const __half* A0 = (const __half*)g_agg1h + r0c[tl] * 64;
        const __half* A1 = (const __half*)g_agg1h + r1c[tl] * 64;
#pragma unroll
        for (int ks = 0; ks < 4; ks++) {
            int c0i = ks * 16 + t * 2;
            a1f[tl][ks][0] = *(const unsigned*)(A0 + c0i);
            a1f[tl][ks][1] = *(const unsigned*)(A1 + c0i);
            a1f[tl][ks][2] = *(const unsigned*)(A0 + c0i + 8);
            a1f[tl][ks][3] = *(const unsigned*)(A1 + c0i + 8);
        }
    }

    // ---- GEMM1: per nb-pair, 4 chains (2 tiles x e/o); relu+repack immediately ----
    unsigned a2f[2][8][4];
#pragma unroll
    for (int p = 0; p < 8; p++) {
        int nce = (2 * p) * 8 + t * 2, nco = (2 * p + 1) * 8 + t * 2;
        float e[2][4], o[2][4];
#pragma unroll
        for (int tl = 0; tl < 2; tl++) {
            e[tl][0] = bs[nce]; e[tl][1] = bs[nce + 1]; e[tl][2] = e[tl][0]; e[tl][3] = e[tl][1];
            o[tl][0] = bs[nco]; o[tl][1] = bs[nco + 1]; o[tl][2] = o[tl][0]; o[tl][3] = o[tl][1];
        }
#pragma unroll
        for (int k1 = 0; k1 < 4; k1++) {
            uint4 f = F1s[(p * 4 + k1) * 32 + lane];
#pragma unroll
            for (int tl = 0; tl < 2; tl++) {
                mma16816(e[tl][0], e[tl][1], e[tl][2], e[tl][3],
                         a1f[tl][k1][0], a1f[tl][k1][1], a1f[tl][k1][2], a1f[tl][k1][3],
                         f.x, f.y);
                mma16816(o[tl][0], o[tl][1], o[tl][2], o[tl][3],
                         a1f[tl][k1][0], a1f[tl][k1][1], a1f[tl][k1][2], a1f[tl][k1][3],
                         f.z, f.w);
            }
        }
#pragma unroll
        for (int tl = 0; tl < 2; tl++) {
            a2f[tl][p][0] = h2u2(fmaxf(e[tl][0], 0.f), fmaxf(e[tl][1], 0.f));
            a2f[tl][p][1] = h2u2(fmaxf(e[tl][2], 0.f), fmaxf(e[tl][3], 0.f));
            a2f[tl][p][2] = h2u2(fmaxf(o[tl][0], 0.f), fmaxf(o[tl][1], 0.f));
            a2f[tl][p][3] = h2u2(fmaxf(o[tl][2], 0.f), fmaxf(o[tl][3], 0.f));
        }
    }

    // ---- GEMM2: per nb-pair, 4 chains (2 tiles x 2 nb) ----
    float w0[2], w1[2];
#pragma unroll
    for (int tl = 0; tl < 2; tl++) {
        float dv0 = g_dinv[r0c[tl]], dv1 = g_dinv[r1c[tl]];
        w0[tl] = dv0 * dv0; w1[tl] = dv1 * dv1;
    }
    __half* p2h = (__half*)g_p2q;
    __half* a2h = (__half*)g_agg2h;
#pragma unroll
    for (int p = 0; p < 4; p++) {
        float d[2][4], q[2][4];
#pragma unroll
        for (int tl = 0; tl < 2; tl++) {
            d[tl][0] = d[tl][1] = d[tl][2] = d[tl][3] = 0.f;
            q[tl][0] = q[tl][1] = q[tl][2] = q[tl][3] = 0.f;
        }
#pragma unroll
        for (int ks = 0; ks < 8; ks++) {
            uint4 f = F2s[(p * 8 + ks) * 32 + lane];
#pragma unroll
            for (int tl = 0; tl < 2; tl++) {
                mma16816(d[tl][0], d[tl][1], d[tl][2], d[tl][3],
                         a2f[tl][ks][0], a2f[tl][ks][1], a2f[tl][ks][2], a2f[tl][ks][3],
                         f.x, f.y);
                mma16816(q[tl][0], q[tl][1], q[tl][2], q[tl][3],
                         a2f[tl][ks][0], a2f[tl][ks][1], a2f[tl][ks][2], a2f[tl][ks][3],
                         f.z, f.w);
            }
        }
        int nc0 = (2 * p) * 8 + t * 2, nc1 = (2 * p + 1) * 8 + t * 2;
#pragma unroll
        for (int tl = 0; tl < 2; tl++) {
            if (r0[tl] < N) {
                unsigned h0 = h2u2(d[tl][0], d[tl][1]);
                unsigned hq = h2u2(q[tl][0], q[tl][1]);
                *(unsigned*)&p2h[r0[tl] * 64 + nc0] = h0;
                *(unsigned*)&p2h[r0[tl] * 64 + nc1] = hq;
                *(unsigned*)&a2h[r0[tl] * 64 + nc0] = h2u2(d[tl][0] * w0[tl], d[tl][1] * w0[tl]);
                *(unsigned*)&a2h[r0[tl] * 64 + nc1] = h2u2(q[tl][0] * w0[tl], q[tl][1] * w0[tl]);
            }
            if (r1[tl] < N) {
                unsigned h1 = h2u2(d[tl][2], d[tl][3]);
                unsigned hr = h2u2(q[tl][2], q[tl][3]);
                *(unsigned*)&p2h[r1[tl] * 64 + nc0] = h1;
                *(unsigned*)&p2h[r1[tl] * 64 + nc1] = hr;
                *(unsigned*)&a2h[r1[tl] * 64 + nc0] = h2u2(d[tl][2] * w1[tl], d[tl][3] * w1[tl]);
                *(unsigned*)&a2h[r1[tl] * 64 + nc1] = h2u2(q[tl][2] * w1[tl], q[tl][3] * w1[tl]);
            }
        }
    }
}

// per-node readout: pAB[n] = (dot(relu(agg2+b2), Wc[:64]), dot(relu(agg2+b2), Wc[64:]))
__global__ void __launch_bounds__(256) k_nodescore(const float* __restrict__ Wc,
                                                   const float* __restrict__ b2, int N) {
    int tid = threadIdx.x;
    int l = tid & 15;
    int row = blockIdx.x * 16 + (tid >> 4);
    if (row >= N) return;
    float4 wa = __ldg((const float4*)Wc + l);
    float4 wb = __ldg((const float4*)Wc + 16 + l);
    float4 b4 = __ldg((const float4*)b2 + l);
    float4 v = from_h4(((const uint2*)g_agg2h)[(size_t)row * 16 + l]);
    v.x = fmaxf(v.x + b4.x, 0.f); v.y = fmaxf(v.y + b4.y, 0.f);
    v.z = fmaxf(v.z + b4.z, 0.f); v.w = fmaxf(v.w + b4.w, 0.f);
    float pa = v.x * wa.x + v.y * wa.y + v.z * wa.z + v.w * wa.w;
    float pb = v.x * wb.x + v.y * wb.y + v.z * wb.z + v.w * wb.w;
#pragma unroll
    for (int o = 8; o >= 1; o >>= 1) {
        pa += __shfl_down_sync(0xffffffffu, pa, o, 16);
        pb += __shfl_down_sync(0xffffffffu, pb, o, 16);
    }
    if (l == 0) g_pAB[row] = make_float2(pa, pb);
}

__global__ void __launch_bounds__(256) k_edge(const float* __restrict__ bcp,
                                              float* __restrict__ out, int E) {
    long e = (long)blockIdx.x * 256 + threadIdx.x;
    if (e >= E) return;
    int s = g_src[e], d = g_dst[e];
    float2 ps = __ldg(&g_pAB[s]);
    float2 pd = __ldg(&g_pAB[d]);
    float z = ps.x + pd.y + __ldg(bcp);
    out[e] = 1.0f / (1.0f + __expf(-z));
}

// ---------------- launcher ----------------
extern "C" void kernel_launch(void* const* d_in, const int* in_sizes, int n_in,
                              void* d_out, int out_size) {
    const float* x  = (const float*)d_in[0];
    const void*  ei = d_in[1];
    const float* W1 = (const float*)d_in[2];
    const float* b1 = (const float*)d_in[3];
    const float* W2 = (const float*)d_in[4];
    const float* b2 = (const float*)d_in[5];
    const float* Wc = (const float*)d_in[6];
    const float* bc = (const float*)d_in[7];
    float* out = (float*)d_out;

    int N = in_sizes[0] / 64;
    int E = in_sizes[1] / 2;
    if (N > N_MAX) N = N_MAX;
    if (E > E_MAX) E = E_MAX;

    int eb128 = (E + 127) / 128;    // 32 groups x 4 edges per block
    int nb16  = (N + 15) / 16;
    int gb    = (N + 255) / 256;    // 256 rows per block
    int ebs   = (E + 255) / 256;

    k_convert  <<<ebs, 256>>>(ei, E);
    k_wprep    <<<8, 256>>>(W1, W2);
    k_prep     <<<nb16, 256>>>(x, N);
    k_agg      <<<eb128, 256>>>(E, 0);
    k_gemm12   <<<gb, 256>>>(b1, N);
    k_agg      <<<eb128, 256>>>(E, 1);
    k_nodescore<<<nb16, 256>>>(Wc, b2, N);
    k_edge     <<<ebs, 256>>>(bc, out, E);
}